// round 1
// baseline (speedup 1.0000x reference)
#include <cuda_runtime.h>
#include <math.h>

#define BATCH   2
#define TSEQ    2048
#define CDIM    1024
#define NHEAD   16
#define HDIM    64

// Scratch: Q,K,V as [B, H, T, D]; attention output as [B, T, C].
__device__ float g_q[BATCH * NHEAD * TSEQ * HDIM];
__device__ float g_k[BATCH * NHEAD * TSEQ * HDIM];
__device__ float g_v[BATCH * NHEAD * TSEQ * HDIM];
__device__ float g_attn[BATCH * TSEQ * CDIM];

// ---------------------------------------------------------------------------
// QKV GEMM: [4096, 1024] @ [1024, 3072] + bias -> scattered into g_q/g_k/g_v
// Tile: BM=64, BN=64, BK=16, 256 threads, 4x4 per thread.
// ---------------------------------------------------------------------------
__global__ __launch_bounds__(256)
void qkv_gemm_kernel(const float* __restrict__ x,
                     const float* __restrict__ w,
                     const float* __restrict__ bias) {
    __shared__ float As[16][65];   // As[k][m] (transposed A tile)
    __shared__ float Bs[16][68];   // Bs[k][n]

    const int tid = threadIdx.x;
    const int tx  = tid & 15;
    const int ty  = tid >> 4;
    const int nb  = blockIdx.x;         // 0..47 (n tile)
    const int m0  = blockIdx.y * 64;    // m tile base
    const int n0  = nb * 64;
    const int K   = CDIM;
    const int N   = 3 * CDIM;

    const int a_row = tid >> 2;          // 0..63
    const int a_k   = (tid & 3) * 4;     // 0,4,8,12
    const int b_k   = tid >> 4;          // 0..15
    const int b_n   = (tid & 15) * 4;

    float acc[4][4] = {};

    for (int k0 = 0; k0 < K; k0 += 16) {
        float4 av = *reinterpret_cast<const float4*>(&x[(m0 + a_row) * K + k0 + a_k]);
        As[a_k + 0][a_row] = av.x;
        As[a_k + 1][a_row] = av.y;
        As[a_k + 2][a_row] = av.z;
        As[a_k + 3][a_row] = av.w;

        float4 bv = *reinterpret_cast<const float4*>(&w[(k0 + b_k) * N + n0 + b_n]);
        Bs[b_k][b_n + 0] = bv.x;
        Bs[b_k][b_n + 1] = bv.y;
        Bs[b_k][b_n + 2] = bv.z;
        Bs[b_k][b_n + 3] = bv.w;
        __syncthreads();

        #pragma unroll
        for (int kk = 0; kk < 16; kk++) {
            float a[4], b[4];
            #pragma unroll
            for (int i = 0; i < 4; i++) a[i] = As[kk][ty * 4 + i];
            #pragma unroll
            for (int j = 0; j < 4; j++) b[j] = Bs[kk][tx * 4 + j];
            #pragma unroll
            for (int i = 0; i < 4; i++)
                #pragma unroll
                for (int j = 0; j < 4; j++)
                    acc[i][j] += a[i] * b[j];
        }
        __syncthreads();
    }

    // Scatter epilogue: per n-tile, slot/head are constant.
    const int slot = nb >> 4;     // 0=Q, 1=K, 2=V
    const int h    = nb & 15;
    float* dst = (slot == 0) ? g_q : (slot == 1) ? g_k : g_v;

    #pragma unroll
    for (int i = 0; i < 4; i++) {
        const int m  = m0 + ty * 4 + i;
        const int bb = m >> 11;           // / 2048
        const int t  = m & 2047;
        #pragma unroll
        for (int j = 0; j < 4; j++) {
            const int d = tx * 4 + j;     // head-dim index (n0 % 64 == 0)
            const float val = acc[i][j] + bias[n0 + d];
            dst[((bb * NHEAD + h) * TSEQ + t) * HDIM + d] = val;
        }
    }
}

// ---------------------------------------------------------------------------
// Flash-style attention: one CTA per (b, h, 64-query tile). Online softmax.
// smem: Qs[64][64], KVs[64][65] (K then V), Ss[64][65], row stats.
// ---------------------------------------------------------------------------
#define ATTN_SMEM_FLOATS (64*64 + 64*65 + 64*65 + 3*64)
#define ATTN_SMEM_BYTES  (ATTN_SMEM_FLOATS * 4)

__global__ __launch_bounds__(256)
void attn_kernel() {
    extern __shared__ float sm[];
    float* Qs   = sm;                    // 64*64, stride 64
    float* KVs  = Qs + 64 * 64;          // 64*65
    float* Ss   = KVs + 64 * 65;         // 64*65
    float* mrow = Ss + 64 * 65;          // 64
    float* lrow = mrow + 64;             // 64
    float* arow = lrow + 64;             // 64

    const int tid = threadIdx.x;
    const int tx  = tid & 15;
    const int ty  = tid >> 4;
    const int qt  = blockIdx.x;          // 0..31
    const int h   = blockIdx.y;          // 0..15
    const int b   = blockIdx.z;          // 0..1

    const float* Qg = g_q + ((size_t)(b * NHEAD + h) * TSEQ + qt * 64) * HDIM;
    const float* Kg = g_k + (size_t)(b * NHEAD + h) * TSEQ * HDIM;
    const float* Vg = g_v + (size_t)(b * NHEAD + h) * TSEQ * HDIM;

    // Load Q tile (64x64), stride-64 smem, vectorized.
    #pragma unroll
    for (int it = 0; it < 4; it++) {
        const int chunk = it * 256 + tid;        // 0..1023 float4 chunks
        const int row   = chunk >> 4;
        const int d4    = (chunk & 15) * 4;
        float4 v = *reinterpret_cast<const float4*>(&Qg[row * HDIM + d4]);
        *reinterpret_cast<float4*>(&Qs[row * 64 + d4]) = v;
    }
    if (tid < 64) { mrow[tid] = -1e30f; lrow[tid] = 0.0f; }

    float O[4][4] = {};
    const float scale = 0.125f;   // 1/sqrt(64)

    for (int kt = 0; kt < 32; kt++) {
        // Load K tile into KVs
        #pragma unroll
        for (int it = 0; it < 4; it++) {
            const int chunk = it * 256 + tid;
            const int row   = chunk >> 4;
            const int d4    = (chunk & 15) * 4;
            float4 v = *reinterpret_cast<const float4*>(&Kg[(kt * 64 + row) * HDIM + d4]);
            KVs[row * 65 + d4 + 0] = v.x;
            KVs[row * 65 + d4 + 1] = v.y;
            KVs[row * 65 + d4 + 2] = v.z;
            KVs[row * 65 + d4 + 3] = v.w;
        }
        __syncthreads();

        // S = scale * Q K^T  (each thread 4x4)
        float acc[4][4] = {};
        #pragma unroll
        for (int d = 0; d < 64; d++) {
            float a[4], kr[4];
            #pragma unroll
            for (int i = 0; i < 4; i++) a[i] = Qs[(ty * 4 + i) * 64 + d];
            #pragma unroll
            for (int j = 0; j < 4; j++) kr[j] = KVs[(tx * 4 + j) * 65 + d];
            #pragma unroll
            for (int i = 0; i < 4; i++)
                #pragma unroll
                for (int j = 0; j < 4; j++)
                    acc[i][j] += a[i] * kr[j];
        }
        #pragma unroll
        for (int i = 0; i < 4; i++)
            #pragma unroll
            for (int j = 0; j < 4; j++)
                Ss[(ty * 4 + i) * 65 + tx * 4 + j] = acc[i][j] * scale;
        __syncthreads();

        // Load V tile (overwrites K data) + per-row max update.
        #pragma unroll
        for (int it = 0; it < 4; it++) {
            const int chunk = it * 256 + tid;
            const int row   = chunk >> 4;
            const int d4    = (chunk & 15) * 4;
            float4 v = *reinterpret_cast<const float4*>(&Vg[(kt * 64 + row) * HDIM + d4]);
            KVs[row * 65 + d4 + 0] = v.x;
            KVs[row * 65 + d4 + 1] = v.y;
            KVs[row * 65 + d4 + 2] = v.z;
            KVs[row * 65 + d4 + 3] = v.w;
        }
        if (tid < 64) {
            float mt = -1e30f;
            #pragma unroll 8
            for (int c = 0; c < 64; c++) mt = fmaxf(mt, Ss[tid * 65 + c]);
            const float mn = fmaxf(mrow[tid], mt);
            arow[tid] = __expf(mrow[tid] - mn);
            mrow[tid] = mn;
        }
        __syncthreads();

        // Exponentiate scores in place; rescale running O.
        float al[4], mm[4];
        #pragma unroll
        for (int i = 0; i < 4; i++) { al[i] = arow[ty * 4 + i]; mm[i] = mrow[ty * 4 + i]; }
        #pragma unroll
        for (int i = 0; i < 4; i++)
            #pragma unroll
            for (int j = 0; j < 4; j++) {
                const int idx = (ty * 4 + i) * 65 + tx * 4 + j;
                Ss[idx] = __expf(Ss[idx] - mm[i]);
                O[i][j] *= al[i];
            }
        __syncthreads();

        // Row-sum update (threads 0..63) + P @ V accumulation (all threads).
        if (tid < 64) {
            float s = 0.0f;
            #pragma unroll 8
            for (int c = 0; c < 64; c++) s += Ss[tid * 65 + c];
            lrow[tid] = lrow[tid] * arow[tid] + s;
        }
        #pragma unroll 4
        for (int kk = 0; kk < 64; kk++) {
            float p[4], vv[4];
            #pragma unroll
            for (int i = 0; i < 4; i++) p[i] = Ss[(ty * 4 + i) * 65 + kk];
            #pragma unroll
            for (int j = 0; j < 4; j++) vv[j] = KVs[kk * 65 + tx * 4 + j];
            #pragma unroll
            for (int i = 0; i < 4; i++)
                #pragma unroll
                for (int j = 0; j < 4; j++)
                    O[i][j] += p[i] * vv[j];
        }
        __syncthreads();
    }

    // Normalize and write to g_attn[B, T, C] with C index = h*64 + d.
    #pragma unroll
    for (int i = 0; i < 4; i++) {
        const int row = ty * 4 + i;
        const float inv = 1.0f / lrow[row];
        #pragma unroll
        for (int j = 0; j < 4; j++) {
            const int d = tx * 4 + j;
            g_attn[((size_t)b * TSEQ + qt * 64 + row) * CDIM + h * HDIM + d] = O[i][j] * inv;
        }
    }
}

// ---------------------------------------------------------------------------
// Output projection: g_attn [4096, 1024] @ w_proj [1024, 1024] + bias -> out
// ---------------------------------------------------------------------------
__global__ __launch_bounds__(256)
void proj_gemm_kernel(const float* __restrict__ w,
                      const float* __restrict__ bias,
                      float* __restrict__ out) {
    __shared__ float As[16][65];
    __shared__ float Bs[16][68];

    const int tid = threadIdx.x;
    const int tx  = tid & 15;
    const int ty  = tid >> 4;
    const int n0  = blockIdx.x * 64;
    const int m0  = blockIdx.y * 64;
    const int K   = CDIM;
    const int N   = CDIM;

    const int a_row = tid >> 2;
    const int a_k   = (tid & 3) * 4;
    const int b_k   = tid >> 4;
    const int b_n   = (tid & 15) * 4;

    float acc[4][4] = {};

    for (int k0 = 0; k0 < K; k0 += 16) {
        float4 av = *reinterpret_cast<const float4*>(&g_attn[(size_t)(m0 + a_row) * K + k0 + a_k]);
        As[a_k + 0][a_row] = av.x;
        As[a_k + 1][a_row] = av.y;
        As[a_k + 2][a_row] = av.z;
        As[a_k + 3][a_row] = av.w;

        float4 bv = *reinterpret_cast<const float4*>(&w[(k0 + b_k) * N + n0 + b_n]);
        Bs[b_k][b_n + 0] = bv.x;
        Bs[b_k][b_n + 1] = bv.y;
        Bs[b_k][b_n + 2] = bv.z;
        Bs[b_k][b_n + 3] = bv.w;
        __syncthreads();

        #pragma unroll
        for (int kk = 0; kk < 16; kk++) {
            float a[4], b[4];
            #pragma unroll
            for (int i = 0; i < 4; i++) a[i] = As[kk][ty * 4 + i];
            #pragma unroll
            for (int j = 0; j < 4; j++) b[j] = Bs[kk][tx * 4 + j];
            #pragma unroll
            for (int i = 0; i < 4; i++)
                #pragma unroll
                for (int j = 0; j < 4; j++)
                    acc[i][j] += a[i] * b[j];
        }
        __syncthreads();
    }

    #pragma unroll
    for (int i = 0; i < 4; i++) {
        const int m = m0 + ty * 4 + i;
        #pragma unroll
        for (int j = 0; j < 4; j++) {
            const int n = n0 + tx * 4 + j;
            out[(size_t)m * N + n] = acc[i][j] + bias[n];
        }
    }
}

// ---------------------------------------------------------------------------
// Launch
// ---------------------------------------------------------------------------
extern "C" void kernel_launch(void* const* d_in, const int* in_sizes, int n_in,
                              void* d_out, int out_size) {
    (void)in_sizes; (void)n_in; (void)out_size;
    const float* x      = (const float*)d_in[0];
    const float* w_qkv  = (const float*)d_in[1];
    const float* b_qkv  = (const float*)d_in[2];
    const float* w_proj = (const float*)d_in[3];
    const float* b_proj = (const float*)d_in[4];
    float* out = (float*)d_out;

    // Idempotent, capture-safe (not a stream op).
    cudaFuncSetAttribute(attn_kernel, cudaFuncAttributeMaxDynamicSharedMemorySize,
                         ATTN_SMEM_BYTES);

    // QKV GEMM: M=4096, N=3072 -> grid (48, 64)
    qkv_gemm_kernel<<<dim3(48, 64), 256>>>(x, w_qkv, b_qkv);

    // Attention: (q tiles, heads, batch)
    attn_kernel<<<dim3(TSEQ / 64, NHEAD, BATCH), 256, ATTN_SMEM_BYTES>>>();

    // Projection: M=4096, N=1024 -> grid (16, 64)
    proj_gemm_kernel<<<dim3(16, 64), 256>>>(w_proj, b_proj, out);
}

// round 3
// speedup vs baseline: 2.8472x; 2.8472x over previous
#include <cuda_runtime.h>
#include <cuda_bf16.h>
#include <math.h>
#include <cstdint>

#define BATCH   2
#define TSEQ    2048
#define CDIM    1024
#define NHEAD   16
#define HDIM    64

typedef __nv_bfloat16 bf16;

// ---------------------------------------------------------------------------
// Scratch (__device__ globals; no allocation allowed)
// ---------------------------------------------------------------------------
#define QKV_ELEMS (BATCH * NHEAD * TSEQ * HDIM)
__device__ __align__(128) bf16 g_x_hi[4096 * 1024];
__device__ __align__(128) bf16 g_x_lo[4096 * 1024];
__device__ __align__(128) bf16 g_wq_hi[3072 * 1024];   // transposed [N][K]
__device__ __align__(128) bf16 g_wq_lo[3072 * 1024];
__device__ __align__(128) bf16 g_wp_hi[1024 * 1024];   // transposed [N][K]
__device__ __align__(128) bf16 g_wp_lo[1024 * 1024];
__device__ __align__(128) bf16 g_q_hi[QKV_ELEMS];      // [B,H,T,D], scale folded
__device__ __align__(128) bf16 g_q_lo[QKV_ELEMS];
__device__ __align__(128) bf16 g_k_hi[QKV_ELEMS];
__device__ __align__(128) bf16 g_k_lo[QKV_ELEMS];
__device__ __align__(128) bf16 g_v_hi[QKV_ELEMS];
__device__ __align__(128) bf16 g_v_lo[QKV_ELEMS];
__device__ __align__(128) bf16 g_at_hi[4096 * 1024];   // attention out [B,T,C]
__device__ __align__(128) bf16 g_at_lo[4096 * 1024];

// ---------------------------------------------------------------------------
// Helpers
// ---------------------------------------------------------------------------
__device__ __forceinline__ uint32_t smem_u32(const void* p) {
    uint32_t a;
    asm("{ .reg .u64 t; cvta.to.shared.u64 t, %1; cvt.u32.u64 %0, t; }" : "=r"(a) : "l"(p));
    return a;
}

__device__ __forceinline__ void cp16(uint32_t dst, const void* src) {
    asm volatile("cp.async.cg.shared.global [%0], [%1], 16;" :: "r"(dst), "l"(src));
}
#define CP_COMMIT() asm volatile("cp.async.commit_group;" ::: "memory")
template <int N>
__device__ __forceinline__ void cp_wait() {
    asm volatile("cp.async.wait_group %0;" :: "n"(N) : "memory");
}

__device__ __forceinline__ void ldsm_x4(uint32_t* r, uint32_t addr) {
    asm volatile("ldmatrix.sync.aligned.m8n8.x4.shared.b16 {%0,%1,%2,%3}, [%4];"
                 : "=r"(r[0]), "=r"(r[1]), "=r"(r[2]), "=r"(r[3]) : "r"(addr));
}
__device__ __forceinline__ void ldsm_x4_t(uint32_t* r, uint32_t addr) {
    asm volatile("ldmatrix.sync.aligned.m8n8.x4.trans.shared.b16 {%0,%1,%2,%3}, [%4];"
                 : "=r"(r[0]), "=r"(r[1]), "=r"(r[2]), "=r"(r[3]) : "r"(addr));
}

// D += A * B, m16n8k16 bf16 -> f32
__device__ __forceinline__ void mma_bf16(float* c, const uint32_t* a,
                                         uint32_t b0, uint32_t b1) {
    asm volatile(
        "mma.sync.aligned.m16n8k16.row.col.f32.bf16.bf16.f32 "
        "{%0,%1,%2,%3}, {%4,%5,%6,%7}, {%8,%9}, {%0,%1,%2,%3};"
        : "+f"(c[0]), "+f"(c[1]), "+f"(c[2]), "+f"(c[3])
        : "r"(a[0]), "r"(a[1]), "r"(a[2]), "r"(a[3]), "r"(b0), "r"(b1));
}

// pack (lo, hi) -> bf16x2 (first PTX source goes to the upper half)
__device__ __forceinline__ uint32_t pk(float lo, float hi) {
    uint32_t r;
    asm("cvt.rn.bf16x2.f32 %0, %1, %2;" : "=r"(r) : "f"(hi), "f"(lo));
    return r;
}
__device__ __forceinline__ float bf_lo(uint32_t v) { return __uint_as_float(v << 16); }
__device__ __forceinline__ float bf_hi(uint32_t v) { return __uint_as_float(v & 0xffff0000u); }

// split float4 into hi/lo bf16x2 pairs
__device__ __forceinline__ void split4(float4 v, uint32_t& hA, uint32_t& hB,
                                       uint32_t& lA, uint32_t& lB) {
    hA = pk(v.x, v.y);
    hB = pk(v.z, v.w);
    lA = pk(v.x - bf_lo(hA), v.y - bf_hi(hA));
    lB = pk(v.z - bf_lo(hB), v.w - bf_hi(hB));
}

// ---------------------------------------------------------------------------
// Conversion kernels
// ---------------------------------------------------------------------------
__global__ __launch_bounds__(256)
void split_kernel(const float* __restrict__ src, bf16* __restrict__ hi,
                  bf16* __restrict__ lo, int n) {
    int i = (blockIdx.x * 256 + threadIdx.x) * 4;
    if (i >= n) return;
    float4 v = *reinterpret_cast<const float4*>(&src[i]);
    uint32_t hA, hB, lA, lB;
    split4(v, hA, hB, lA, lB);
    *reinterpret_cast<uint2*>(&hi[i]) = make_uint2(hA, hB);
    *reinterpret_cast<uint2*>(&lo[i]) = make_uint2(lA, lB);
}

// Transpose + split: src f32 [K][N] -> hi/lo bf16 [N][K]
__global__ __launch_bounds__(256)
void transpose_split_kernel(const float* __restrict__ src, bf16* __restrict__ hi,
                            bf16* __restrict__ lo, int K, int N) {
    __shared__ float tile[32][33];
    const int bx = blockIdx.x * 32;   // n base
    const int by = blockIdx.y * 32;   // k base
    const int x = threadIdx.x;
    const int y = threadIdx.y;
    #pragma unroll
    for (int j = 0; j < 32; j += 8)
        tile[y + j][x] = src[(size_t)(by + y + j) * N + bx + x];
    __syncthreads();
    #pragma unroll
    for (int j = 0; j < 32; j += 8) {
        float v = tile[x][y + j];
        bf16 h = __float2bfloat16(v);
        bf16 l = __float2bfloat16(v - __bfloat162float(h));
        size_t o = (size_t)(bx + y + j) * K + by + x;
        hi[o] = h;
        lo[o] = l;
    }
}

// ---------------------------------------------------------------------------
// GEMM via mma.sync bf16x3: C[M,N] = A[M,K=1024] @ B[N,K]^T + bias
// CTA 128x128, 8 warps (4x2), BK=32, double-buffered cp.async.
// KIND 0: QKV (scatter + hi/lo split, Q scale folded). KIND 1: proj (f32 out).
// ---------------------------------------------------------------------------
#define APAD 40
#define MAT_BYTES (128 * APAD * 2)       // 10240
#define STG_BYTES (4 * MAT_BYTES)        // 40960
#define GEMM_SMEM (2 * STG_BYTES)        // 81920 (>= 128*132*4 epilogue)

#define QSCALE 0.1803368801111f          // 0.125 * log2(e)

template <int KIND>
__global__ __launch_bounds__(256)
void mma_gemm(const bf16* __restrict__ a_hi, const bf16* __restrict__ a_lo,
              const bf16* __restrict__ b_hi, const bf16* __restrict__ b_lo,
              const float* __restrict__ bias, float* __restrict__ out) {
    extern __shared__ char smem[];
    const uint32_t sb = smem_u32(smem);
    const int tid = threadIdx.x;
    const int lane = tid & 31;
    const int wid = tid >> 5;
    const int wm = wid & 3;          // 0..3
    const int wn = wid >> 2;         // 0..1
    const int n0 = blockIdx.x * 128;
    const int m0 = blockIdx.y * 128;
    const int NCH = 32;              // 1024 / 32

    auto load_chunk = [&](int ch, int stg) {
        const uint32_t base = sb + stg * STG_BYTES;
        const int k0 = ch * 32;
        #pragma unroll
        for (int i = 0; i < 2; i++) {
            const int idx = tid + i * 256;     // 0..511
            const int r = idx >> 2;            // 0..127
            const int c = idx & 3;             // 4 x 16B per 32-col row
            const uint32_t off = r * (APAD * 2) + c * 16;
            const size_t ga = (size_t)(m0 + r) * 1024 + k0 + c * 8;
            const size_t gb = (size_t)(n0 + r) * 1024 + k0 + c * 8;
            cp16(base + 0 * MAT_BYTES + off, a_hi + ga);
            cp16(base + 1 * MAT_BYTES + off, a_lo + ga);
            cp16(base + 2 * MAT_BYTES + off, b_hi + gb);
            cp16(base + 3 * MAT_BYTES + off, b_lo + gb);
        }
        CP_COMMIT();
    };

    float acc[2][8][4] = {};
    load_chunk(0, 0);
    load_chunk(1, 1);

    for (int ch = 0; ch < NCH; ch++) {
        if (ch < NCH - 1) cp_wait<1>(); else cp_wait<0>();
        __syncthreads();
        const uint32_t base = sb + (ch & 1) * STG_BYTES;
        #pragma unroll
        for (int ks = 0; ks < 2; ks++) {
            uint32_t ah[2][4], al[2][4];
            #pragma unroll
            for (int mt = 0; mt < 2; mt++) {
                const uint32_t addr = base +
                    (wm * 32 + mt * 16 + (lane & 15)) * (APAD * 2) +
                    (ks * 16 + (lane >> 4) * 8) * 2;
                ldsm_x4(ah[mt], addr);
                ldsm_x4(al[mt], addr + MAT_BYTES);
            }
            #pragma unroll
            for (int bp = 0; bp < 4; bp++) {
                uint32_t bh[4], bl[4];
                const uint32_t addr = base + 2 * MAT_BYTES +
                    (wn * 64 + bp * 16 + (lane & 15)) * (APAD * 2) +
                    (ks * 16 + (lane >> 4) * 8) * 2;
                ldsm_x4(bh, addr);
                ldsm_x4(bl, addr + MAT_BYTES);
                #pragma unroll
                for (int mt = 0; mt < 2; mt++) {
                    mma_bf16(acc[mt][2 * bp + 0], ah[mt], bh[0], bh[2]);
                    mma_bf16(acc[mt][2 * bp + 0], ah[mt], bl[0], bl[2]);
                    mma_bf16(acc[mt][2 * bp + 0], al[mt], bh[0], bh[2]);
                    mma_bf16(acc[mt][2 * bp + 1], ah[mt], bh[1], bh[3]);
                    mma_bf16(acc[mt][2 * bp + 1], ah[mt], bl[1], bl[3]);
                    mma_bf16(acc[mt][2 * bp + 1], al[mt], bh[1], bh[3]);
                }
            }
        }
        __syncthreads();
        if (ch + 2 < NCH) load_chunk(ch + 2, ch & 1);
    }

    // Epilogue: stage fp32 C in smem, then coalesced writes.
    float* sC = reinterpret_cast<float*>(smem);   // [128][132]
    #pragma unroll
    for (int mt = 0; mt < 2; mt++)
        #pragma unroll
        for (int nt = 0; nt < 8; nt++) {
            const int r = wm * 32 + mt * 16 + (lane >> 2);
            const int c = wn * 64 + nt * 8 + 2 * (lane & 3);
            sC[r * 132 + c]           = acc[mt][nt][0];
            sC[r * 132 + c + 1]       = acc[mt][nt][1];
            sC[(r + 8) * 132 + c]     = acc[mt][nt][2];
            sC[(r + 8) * 132 + c + 1] = acc[mt][nt][3];
        }
    __syncthreads();

    #pragma unroll
    for (int it = 0; it < 16; it++) {
        const int idx = tid + it * 256;     // 0..4095
        const int r = idx >> 5;
        const int c4 = (idx & 31) * 4;
        float4 v = *reinterpret_cast<float4*>(&sC[r * 132 + c4]);
        const float4 bb = *reinterpret_cast<const float4*>(&bias[n0 + c4]);
        v.x += bb.x; v.y += bb.y; v.z += bb.z; v.w += bb.w;
        const int m = m0 + r;
        if (KIND == 0) {
            const int n = n0 + c4;
            const int slot = n >> 10;
            const int h = (n >> 6) & 15;
            const int d = n & 63;
            const int b = m >> 11;
            const int t = m & 2047;
            const size_t o = ((size_t)(b * NHEAD + h) * TSEQ + t) * HDIM + d;
            bf16 *dh, *dl;
            if (slot == 0) {
                dh = g_q_hi; dl = g_q_lo;
                v.x *= QSCALE; v.y *= QSCALE; v.z *= QSCALE; v.w *= QSCALE;
            } else if (slot == 1) { dh = g_k_hi; dl = g_k_lo; }
            else                  { dh = g_v_hi; dl = g_v_lo; }
            uint32_t hA, hB, lA, lB;
            split4(v, hA, hB, lA, lB);
            *reinterpret_cast<uint2*>(&dh[o]) = make_uint2(hA, hB);
            *reinterpret_cast<uint2*>(&dl[o]) = make_uint2(lA, lB);
        } else {
            *reinterpret_cast<float4*>(&out[(size_t)m * 1024 + n0 + c4]) = v;
        }
    }
}

// ---------------------------------------------------------------------------
// Flash attention via mma.sync bf16x3. CTA: 4 warps, 64 q-rows.
// Warp w owns q rows [16w, 16w+16). K/V tiles (64 keys) double-buffered.
// Scores are in log2-units (scale*log2e folded into Q) -> exp2f softmax.
// ---------------------------------------------------------------------------
#define KVPAD 72
#define QMAT_BYTES (64 * KVPAD * 2)           // 9216
#define KV_STG_BYTES (4 * QMAT_BYTES)         // 36864
#define ATTN_SMEM (2 * QMAT_BYTES + 2 * KV_STG_BYTES)  // 92160

__global__ __launch_bounds__(128)
void attn_kernel() {
    extern __shared__ char smem[];
    const uint32_t sb = smem_u32(smem);
    const int tid = threadIdx.x;
    const int lane = tid & 31;
    const int w = tid >> 5;            // 0..3
    const int qt = blockIdx.x;         // 0..31
    const int h  = blockIdx.y;
    const int b  = blockIdx.z;

    const size_t head_off = (size_t)(b * NHEAD + h) * TSEQ * HDIM;
    const size_t q_off = head_off + (size_t)qt * 64 * HDIM;

    const uint32_t sQh = sb;
    const uint32_t sQl = sb + QMAT_BYTES;

    // Q tile load (hi+lo): 64 rows x 64 cols, 8 chunks of 16B per row.
    {
        #pragma unroll
        for (int i = 0; i < 4; i++) {
            const int idx = tid + i * 128;     // 0..511
            const int r = idx >> 3;
            const int c = idx & 7;
            const uint32_t off = r * (KVPAD * 2) + c * 16;
            const size_t g = q_off + (size_t)r * HDIM + c * 8;
            cp16(sQh + off, g_q_hi + g);
            cp16(sQl + off, g_q_lo + g);
        }
    }

    auto load_kv = [&](int kt, int stg) {
        const uint32_t base = sb + 2 * QMAT_BYTES + stg * KV_STG_BYTES;
        #pragma unroll
        for (int i = 0; i < 4; i++) {
            const int idx = tid + i * 128;     // 0..511
            const int r = idx >> 3;
            const int c = idx & 7;
            const uint32_t off = r * (KVPAD * 2) + c * 16;
            const size_t g = head_off + (size_t)(kt * 64 + r) * HDIM + c * 8;
            cp16(base + 0 * QMAT_BYTES + off, g_k_hi + g);
            cp16(base + 1 * QMAT_BYTES + off, g_k_lo + g);
            cp16(base + 2 * QMAT_BYTES + off, g_v_hi + g);
            cp16(base + 3 * QMAT_BYTES + off, g_v_lo + g);
        }
        CP_COMMIT();
    };

    load_kv(0, 0);     // Q rides in group 0 with KV(0)
    load_kv(1, 1);

    float o[8][4] = {};
    float m0r = -1e30f, m1r = -1e30f;
    float l0r = 0.0f, l1r = 0.0f;

    for (int kt = 0; kt < 32; kt++) {
        if (kt < 31) cp_wait<1>(); else cp_wait<0>();
        __syncthreads();
        const uint32_t kv = sb + 2 * QMAT_BYTES + (kt & 1) * KV_STG_BYTES;

        // ---- S = Q @ K^T (bf16x3), 16 rows x 64 keys per warp ----
        float s[8][4] = {};
        #pragma unroll
        for (int ks = 0; ks < 4; ks++) {
            uint32_t aqh[4], aql[4];
            const uint32_t qaddr = sQh + (w * 16 + (lane & 15)) * (KVPAD * 2) +
                                   (ks * 16 + (lane >> 4) * 8) * 2;
            ldsm_x4(aqh, qaddr);
            ldsm_x4(aql, qaddr + QMAT_BYTES);
            #pragma unroll
            for (int bp = 0; bp < 4; bp++) {
                uint32_t bh[4], bl[4];
                const uint32_t kaddr = kv + (bp * 16 + (lane & 15)) * (KVPAD * 2) +
                                       (ks * 16 + (lane >> 4) * 8) * 2;
                ldsm_x4(bh, kaddr);
                ldsm_x4(bl, kaddr + QMAT_BYTES);
                mma_bf16(s[2 * bp + 0], aqh, bh[0], bh[2]);
                mma_bf16(s[2 * bp + 0], aqh, bl[0], bl[2]);
                mma_bf16(s[2 * bp + 0], aql, bh[0], bh[2]);
                mma_bf16(s[2 * bp + 1], aqh, bh[1], bh[3]);
                mma_bf16(s[2 * bp + 1], aqh, bl[1], bl[3]);
                mma_bf16(s[2 * bp + 1], aql, bh[1], bh[3]);
            }
        }

        // ---- Online softmax on fragments (rows lane>>2 and lane>>2 + 8) ----
        float tm0 = -1e30f, tm1 = -1e30f;
        #pragma unroll
        for (int nt = 0; nt < 8; nt++) {
            tm0 = fmaxf(tm0, fmaxf(s[nt][0], s[nt][1]));
            tm1 = fmaxf(tm1, fmaxf(s[nt][2], s[nt][3]));
        }
        tm0 = fmaxf(tm0, __shfl_xor_sync(0xffffffffu, tm0, 1));
        tm0 = fmaxf(tm0, __shfl_xor_sync(0xffffffffu, tm0, 2));
        tm1 = fmaxf(tm1, __shfl_xor_sync(0xffffffffu, tm1, 1));
        tm1 = fmaxf(tm1, __shfl_xor_sync(0xffffffffu, tm1, 2));

        const float mn0 = fmaxf(m0r, tm0);
        const float mn1 = fmaxf(m1r, tm1);
        const float al0 = exp2f(m0r - mn0);
        const float al1 = exp2f(m1r - mn1);
        m0r = mn0; m1r = mn1;

        float sum0 = 0.0f, sum1 = 0.0f;
        uint32_t ph[8][2], pl[8][2];
        #pragma unroll
        for (int nt = 0; nt < 8; nt++) {
            const float p0 = exp2f(s[nt][0] - mn0);
            const float p1 = exp2f(s[nt][1] - mn0);
            const float p2 = exp2f(s[nt][2] - mn1);
            const float p3 = exp2f(s[nt][3] - mn1);
            sum0 += p0 + p1;
            sum1 += p2 + p3;
            ph[nt][0] = pk(p0, p1);
            ph[nt][1] = pk(p2, p3);
            pl[nt][0] = pk(p0 - bf_lo(ph[nt][0]), p1 - bf_hi(ph[nt][0]));
            pl[nt][1] = pk(p2 - bf_lo(ph[nt][1]), p3 - bf_hi(ph[nt][1]));
        }
        sum0 += __shfl_xor_sync(0xffffffffu, sum0, 1);
        sum0 += __shfl_xor_sync(0xffffffffu, sum0, 2);
        sum1 += __shfl_xor_sync(0xffffffffu, sum1, 1);
        sum1 += __shfl_xor_sync(0xffffffffu, sum1, 2);
        l0r = l0r * al0 + sum0;
        l1r = l1r * al1 + sum1;

        #pragma unroll
        for (int nt = 0; nt < 8; nt++) {
            o[nt][0] *= al0; o[nt][1] *= al0;
            o[nt][2] *= al1; o[nt][3] *= al1;
        }

        // ---- O += P @ V (bf16x3) ----
        #pragma unroll
        for (int j = 0; j < 4; j++) {          // key 16-step
            uint32_t aPh[4] = { ph[2 * j][0], ph[2 * j][1],
                                ph[2 * j + 1][0], ph[2 * j + 1][1] };
            uint32_t aPl[4] = { pl[2 * j][0], pl[2 * j][1],
                                pl[2 * j + 1][0], pl[2 * j + 1][1] };
            #pragma unroll
            for (int dp = 0; dp < 4; dp++) {   // dim 16-pair
                uint32_t vh[4], vl[4];
                const uint32_t vaddr = kv + 2 * QMAT_BYTES +
                    (j * 16 + (lane & 15)) * (KVPAD * 2) +
                    (dp * 16 + (lane >> 4) * 8) * 2;
                ldsm_x4_t(vh, vaddr);
                ldsm_x4_t(vl, vaddr + QMAT_BYTES);
                mma_bf16(o[2 * dp + 0], aPh, vh[0], vh[1]);
                mma_bf16(o[2 * dp + 0], aPh, vl[0], vl[1]);
                mma_bf16(o[2 * dp + 0], aPl, vh[0], vh[1]);
                mma_bf16(o[2 * dp + 1], aPh, vh[2], vh[3]);
                mma_bf16(o[2 * dp + 1], aPh, vl[2], vl[3]);
                mma_bf16(o[2 * dp + 1], aPl, vh[2], vh[3]);
            }
        }
        __syncthreads();
        if (kt + 2 < 32) load_kv(kt + 2, kt & 1);
    }

    // ---- Normalize + write bf16 hi/lo to g_at [B,T,C] ----
    const float inv0 = 1.0f / l0r;
    const float inv1 = 1.0f / l1r;
    const int row0 = qt * 64 + w * 16 + (lane >> 2);
    #pragma unroll
    for (int nt = 0; nt < 8; nt++) {
        const int col = h * HDIM + nt * 8 + 2 * (lane & 3);
        const size_t o0 = ((size_t)b * TSEQ + row0) * CDIM + col;
        const size_t o1 = ((size_t)b * TSEQ + row0 + 8) * CDIM + col;
        const float v0 = o[nt][0] * inv0, v1 = o[nt][1] * inv0;
        const float v2 = o[nt][2] * inv1, v3 = o[nt][3] * inv1;
        const uint32_t h0 = pk(v0, v1);
        const uint32_t h1 = pk(v2, v3);
        *reinterpret_cast<uint32_t*>(&g_at_hi[o0]) = h0;
        *reinterpret_cast<uint32_t*>(&g_at_hi[o1]) = h1;
        *reinterpret_cast<uint32_t*>(&g_at_lo[o0]) =
            pk(v0 - bf_lo(h0), v1 - bf_hi(h0));
        *reinterpret_cast<uint32_t*>(&g_at_lo[o1]) =
            pk(v2 - bf_lo(h1), v3 - bf_hi(h1));
    }
}

// ---------------------------------------------------------------------------
// Launch
// ---------------------------------------------------------------------------
extern "C" void kernel_launch(void* const* d_in, const int* in_sizes, int n_in,
                              void* d_out, int out_size) {
    (void)in_sizes; (void)n_in; (void)out_size;
    const float* x      = (const float*)d_in[0];
    const float* w_qkv  = (const float*)d_in[1];
    const float* b_qkv  = (const float*)d_in[2];
    const float* w_proj = (const float*)d_in[3];
    const float* b_proj = (const float*)d_in[4];
    float* out = (float*)d_out;

    cudaFuncSetAttribute(mma_gemm<0>, cudaFuncAttributeMaxDynamicSharedMemorySize, GEMM_SMEM);
    cudaFuncSetAttribute(mma_gemm<1>, cudaFuncAttributeMaxDynamicSharedMemorySize, GEMM_SMEM);
    cudaFuncSetAttribute(attn_kernel, cudaFuncAttributeMaxDynamicSharedMemorySize, ATTN_SMEM);

    bf16 *x_hi, *x_lo, *wq_hi, *wq_lo, *wp_hi, *wp_lo, *at_hi, *at_lo;
    cudaGetSymbolAddress((void**)&x_hi,  g_x_hi);
    cudaGetSymbolAddress((void**)&x_lo,  g_x_lo);
    cudaGetSymbolAddress((void**)&wq_hi, g_wq_hi);
    cudaGetSymbolAddress((void**)&wq_lo, g_wq_lo);
    cudaGetSymbolAddress((void**)&wp_hi, g_wp_hi);
    cudaGetSymbolAddress((void**)&wp_lo, g_wp_lo);
    cudaGetSymbolAddress((void**)&at_hi, g_at_hi);
    cudaGetSymbolAddress((void**)&at_lo, g_at_lo);

    // Conversions
    split_kernel<<<4096, 256>>>(x, x_hi, x_lo, 4096 * 1024);
    transpose_split_kernel<<<dim3(96, 32), dim3(32, 8)>>>(w_qkv, wq_hi, wq_lo, 1024, 3072);
    transpose_split_kernel<<<dim3(32, 32), dim3(32, 8)>>>(w_proj, wp_hi, wp_lo, 1024, 1024);

    // QKV GEMM: M=4096, N=3072 -> grid (24, 32)
    mma_gemm<0><<<dim3(24, 32), 256, GEMM_SMEM>>>(x_hi, x_lo, wq_hi, wq_lo, b_qkv, nullptr);

    // Attention: (32 q-tiles, 16 heads, 2 batch)
    attn_kernel<<<dim3(32, NHEAD, BATCH), 128, ATTN_SMEM>>>();

    // Projection: M=4096, N=1024 -> grid (8, 32)
    mma_gemm<1><<<dim3(8, 32), 256, GEMM_SMEM>>>(at_hi, at_lo, wp_hi, wp_lo, b_proj, out);
}

// round 4
// speedup vs baseline: 3.9953x; 1.4032x over previous
#include <cuda_runtime.h>
#include <cuda_bf16.h>
#include <cuda_fp16.h>
#include <math.h>
#include <cstdint>

#define BATCH   2
#define TSEQ    2048
#define CDIM    1024
#define NHEAD   16
#define HDIM    64

typedef __nv_bfloat16 bf16;
typedef __half fp16;

// ---------------------------------------------------------------------------
// Scratch (__device__ globals; no allocation allowed)
// ---------------------------------------------------------------------------
#define QKV_ELEMS (BATCH * NHEAD * TSEQ * HDIM)
__device__ __align__(128) bf16 g_x_hi[4096 * 1024];
__device__ __align__(128) bf16 g_x_lo[4096 * 1024];
__device__ __align__(128) bf16 g_wq_hi[3072 * 1024];   // transposed [N][K]
__device__ __align__(128) bf16 g_wq_lo[3072 * 1024];
__device__ __align__(128) bf16 g_wp_hi[1024 * 1024];   // transposed [N][K]
__device__ __align__(128) bf16 g_wp_lo[1024 * 1024];
__device__ __align__(128) fp16 g_qh[QKV_ELEMS];        // q scaled, fp16 hi
__device__ __align__(128) fp16 g_ql[QKV_ELEMS];        // q scaled, fp16 lo
__device__ __align__(128) fp16 g_k16[QKV_ELEMS];       // k single fp16
__device__ __align__(128) fp16 g_v16[QKV_ELEMS];       // v single fp16
__device__ __align__(128) bf16 g_at_hi[4096 * 1024];   // attention out [B,T,C]
__device__ __align__(128) bf16 g_at_lo[4096 * 1024];

// ---------------------------------------------------------------------------
// Helpers
// ---------------------------------------------------------------------------
__device__ __forceinline__ uint32_t smem_u32(const void* p) {
    uint32_t a;
    asm("{ .reg .u64 t; cvta.to.shared.u64 t, %1; cvt.u32.u64 %0, t; }" : "=r"(a) : "l"(p));
    return a;
}

__device__ __forceinline__ void cp16(uint32_t dst, const void* src) {
    asm volatile("cp.async.cg.shared.global [%0], [%1], 16;" :: "r"(dst), "l"(src));
}
#define CP_COMMIT() asm volatile("cp.async.commit_group;" ::: "memory")
template <int N>
__device__ __forceinline__ void cp_wait() {
    asm volatile("cp.async.wait_group %0;" :: "n"(N) : "memory");
}

__device__ __forceinline__ void ldsm_x4(uint32_t* r, uint32_t addr) {
    asm volatile("ldmatrix.sync.aligned.m8n8.x4.shared.b16 {%0,%1,%2,%3}, [%4];"
                 : "=r"(r[0]), "=r"(r[1]), "=r"(r[2]), "=r"(r[3]) : "r"(addr));
}
__device__ __forceinline__ void ldsm_x4_t(uint32_t* r, uint32_t addr) {
    asm volatile("ldmatrix.sync.aligned.m8n8.x4.trans.shared.b16 {%0,%1,%2,%3}, [%4];"
                 : "=r"(r[0]), "=r"(r[1]), "=r"(r[2]), "=r"(r[3]) : "r"(addr));
}

// D += A * B, m16n8k16 bf16 -> f32
__device__ __forceinline__ void mma_bf16(float* c, const uint32_t* a,
                                         uint32_t b0, uint32_t b1) {
    asm volatile(
        "mma.sync.aligned.m16n8k16.row.col.f32.bf16.bf16.f32 "
        "{%0,%1,%2,%3}, {%4,%5,%6,%7}, {%8,%9}, {%0,%1,%2,%3};"
        : "+f"(c[0]), "+f"(c[1]), "+f"(c[2]), "+f"(c[3])
        : "r"(a[0]), "r"(a[1]), "r"(a[2]), "r"(a[3]), "r"(b0), "r"(b1));
}
// D += A * B, m16n8k16 fp16 -> f32
__device__ __forceinline__ void mma_fp16(float* c, const uint32_t* a,
                                         uint32_t b0, uint32_t b1) {
    asm volatile(
        "mma.sync.aligned.m16n8k16.row.col.f32.f16.f16.f32 "
        "{%0,%1,%2,%3}, {%4,%5,%6,%7}, {%8,%9}, {%0,%1,%2,%3};"
        : "+f"(c[0]), "+f"(c[1]), "+f"(c[2]), "+f"(c[3])
        : "r"(a[0]), "r"(a[1]), "r"(a[2]), "r"(a[3]), "r"(b0), "r"(b1));
}

// bf16 pack helpers
__device__ __forceinline__ uint32_t pk(float lo, float hi) {
    uint32_t r;
    asm("cvt.rn.bf16x2.f32 %0, %1, %2;" : "=r"(r) : "f"(hi), "f"(lo));
    return r;
}
__device__ __forceinline__ float bf_lo(uint32_t v) { return __uint_as_float(v << 16); }
__device__ __forceinline__ float bf_hi(uint32_t v) { return __uint_as_float(v & 0xffff0000u); }

// fp16 pack helpers
__device__ __forceinline__ uint32_t pkh(float a, float b) {
    __half2 h = __floats2half2_rn(a, b);
    return *reinterpret_cast<uint32_t*>(&h);
}
__device__ __forceinline__ float h_el0(uint32_t v) {
    return __half2float(__ushort_as_half((unsigned short)(v & 0xffffu)));
}
__device__ __forceinline__ float h_el1(uint32_t v) {
    return __half2float(__ushort_as_half((unsigned short)(v >> 16)));
}

// split float4 into hi/lo bf16x2 pairs
__device__ __forceinline__ void split4(float4 v, uint32_t& hA, uint32_t& hB,
                                       uint32_t& lA, uint32_t& lB) {
    hA = pk(v.x, v.y);
    hB = pk(v.z, v.w);
    lA = pk(v.x - bf_lo(hA), v.y - bf_hi(hA));
    lB = pk(v.z - bf_lo(hB), v.w - bf_hi(hB));
}

// swizzles
#define SWZ128(off) ((off) ^ (((off) >> 3) & 0x70))
#define SWZ64(r, c) ((uint32_t)((r) * 64 + ((((c) ^ (((r) >> 1) & 3))) << 4)))

// ---------------------------------------------------------------------------
// Conversion kernels
// ---------------------------------------------------------------------------
__global__ __launch_bounds__(256)
void split_kernel(const float* __restrict__ src, bf16* __restrict__ hi,
                  bf16* __restrict__ lo, int n) {
    int i = (blockIdx.x * 256 + threadIdx.x) * 4;
    if (i >= n) return;
    float4 v = *reinterpret_cast<const float4*>(&src[i]);
    uint32_t hA, hB, lA, lB;
    split4(v, hA, hB, lA, lB);
    *reinterpret_cast<uint2*>(&hi[i]) = make_uint2(hA, hB);
    *reinterpret_cast<uint2*>(&lo[i]) = make_uint2(lA, lB);
}

// Transpose + split: src f32 [K][N] -> hi/lo bf16 [N][K]
__global__ __launch_bounds__(256)
void transpose_split_kernel(const float* __restrict__ src, bf16* __restrict__ hi,
                            bf16* __restrict__ lo, int K, int N) {
    __shared__ float tile[32][33];
    const int bx = blockIdx.x * 32;
    const int by = blockIdx.y * 32;
    const int x = threadIdx.x;
    const int y = threadIdx.y;
    #pragma unroll
    for (int j = 0; j < 32; j += 8)
        tile[y + j][x] = src[(size_t)(by + y + j) * N + bx + x];
    __syncthreads();
    #pragma unroll
    for (int j = 0; j < 32; j += 8) {
        float v = tile[x][y + j];
        bf16 h = __float2bfloat16(v);
        bf16 l = __float2bfloat16(v - __bfloat162float(h));
        size_t o = (size_t)(bx + y + j) * K + by + x;
        hi[o] = h;
        lo[o] = l;
    }
}

// ---------------------------------------------------------------------------
// GEMM via mma.sync bf16x3: C[M,N] = A[M,K=1024] @ B[N,K]^T + bias
// CTA 128x128, 8 warps (4x2), BK=32, 3-stage cp.async, swizzled 64B rows,
// single __syncthreads per chunk.
// KIND 0: QKV scatter (q scaled fp16 hi/lo; k,v single fp16). KIND 1: f32 out.
// ---------------------------------------------------------------------------
#define GM_MAT 8192                    // 128 rows * 64B
#define GM_STG (4 * GM_MAT)            // 32768 (Ah, Al, Bh, Bl)
#define GM_STAGES 3
#define GEMM_SMEM (GM_STAGES * GM_STG) // 98304 (epilogue needs 67.6KB, fits)

#define QSCALE 0.1803368801111f        // 0.125 * log2(e)

template <int KIND>
__global__ __launch_bounds__(256)
void mma_gemm(const bf16* __restrict__ a_hi, const bf16* __restrict__ a_lo,
              const bf16* __restrict__ b_hi, const bf16* __restrict__ b_lo,
              const float* __restrict__ bias, float* __restrict__ out) {
    extern __shared__ char smem[];
    const uint32_t sb = smem_u32(smem);
    const int tid = threadIdx.x;
    const int lane = tid & 31;
    const int wid = tid >> 5;
    const int wm = wid & 3;
    const int wn = wid >> 2;
    const int n0 = blockIdx.x * 128;
    const int m0 = blockIdx.y * 128;
    const int NCH = 32;

    auto load_chunk = [&](int ch, int stg) {
        const uint32_t base = sb + stg * GM_STG;
        const int k0 = ch * 32;
        #pragma unroll
        for (int i = 0; i < 2; i++) {
            const int idx = tid + i * 256;     // 0..511
            const int r = idx >> 2;            // 0..127
            const int c = idx & 3;             // 16B chunk within 64B row
            const uint32_t off = SWZ64(r, c);
            const size_t ga = (size_t)(m0 + r) * 1024 + k0 + c * 8;
            const size_t gb = (size_t)(n0 + r) * 1024 + k0 + c * 8;
            cp16(base + 0 * GM_MAT + off, a_hi + ga);
            cp16(base + 1 * GM_MAT + off, a_lo + ga);
            cp16(base + 2 * GM_MAT + off, b_hi + gb);
            cp16(base + 3 * GM_MAT + off, b_lo + gb);
        }
        CP_COMMIT();
    };

    float acc[2][8][4] = {};
    load_chunk(0, 0);
    load_chunk(1, 1);

    for (int ch = 0; ch < NCH; ch++) {
        if (ch < NCH - 1) cp_wait<1>(); else cp_wait<0>();
        __syncthreads();
        if (ch + 2 < NCH) load_chunk(ch + 2, (ch + 2) % GM_STAGES);

        const uint32_t base = sb + (ch % GM_STAGES) * GM_STG;
        #pragma unroll
        for (int ks = 0; ks < 2; ks++) {
            const int cc = ks * 2 + (lane >> 4);
            uint32_t ah[2][4], al[2][4];
            #pragma unroll
            for (int mt = 0; mt < 2; mt++) {
                const int row = wm * 32 + mt * 16 + (lane & 15);
                const uint32_t addr = base + SWZ64(row, cc);
                ldsm_x4(ah[mt], addr);
                ldsm_x4(al[mt], addr + GM_MAT);
            }
            #pragma unroll
            for (int bp = 0; bp < 4; bp++) {
                uint32_t bh[4], bl[4];
                const int row = wn * 64 + bp * 16 + (lane & 15);
                const uint32_t addr = base + 2 * GM_MAT + SWZ64(row, cc);
                ldsm_x4(bh, addr);
                ldsm_x4(bl, addr + GM_MAT);
                #pragma unroll
                for (int mt = 0; mt < 2; mt++) {
                    mma_bf16(acc[mt][2 * bp + 0], ah[mt], bh[0], bh[2]);
                    mma_bf16(acc[mt][2 * bp + 0], ah[mt], bl[0], bl[2]);
                    mma_bf16(acc[mt][2 * bp + 0], al[mt], bh[0], bh[2]);
                    mma_bf16(acc[mt][2 * bp + 1], ah[mt], bh[1], bh[3]);
                    mma_bf16(acc[mt][2 * bp + 1], ah[mt], bl[1], bl[3]);
                    mma_bf16(acc[mt][2 * bp + 1], al[mt], bh[1], bh[3]);
                }
            }
        }
    }
    __syncthreads();   // mainloop smem reads done before epilogue overwrite

    // Epilogue: stage fp32 C in smem, then coalesced writes.
    float* sC = reinterpret_cast<float*>(smem);   // [128][132]
    #pragma unroll
    for (int mt = 0; mt < 2; mt++)
        #pragma unroll
        for (int nt = 0; nt < 8; nt++) {
            const int r = wm * 32 + mt * 16 + (lane >> 2);
            const int c = wn * 64 + nt * 8 + 2 * (lane & 3);
            sC[r * 132 + c]           = acc[mt][nt][0];
            sC[r * 132 + c + 1]       = acc[mt][nt][1];
            sC[(r + 8) * 132 + c]     = acc[mt][nt][2];
            sC[(r + 8) * 132 + c + 1] = acc[mt][nt][3];
        }
    __syncthreads();

    #pragma unroll
    for (int it = 0; it < 16; it++) {
        const int idx = tid + it * 256;     // 0..4095
        const int r = idx >> 5;
        const int c4 = (idx & 31) * 4;
        float4 v = *reinterpret_cast<float4*>(&sC[r * 132 + c4]);
        const float4 bb = *reinterpret_cast<const float4*>(&bias[n0 + c4]);
        v.x += bb.x; v.y += bb.y; v.z += bb.z; v.w += bb.w;
        const int m = m0 + r;
        if (KIND == 0) {
            const int n = n0 + c4;
            const int slot = n >> 10;
            const int h = (n >> 6) & 15;
            const int d = n & 63;
            const int b = m >> 11;
            const int t = m & 2047;
            const size_t o = ((size_t)(b * NHEAD + h) * TSEQ + t) * HDIM + d;
            if (slot == 0) {
                v.x *= QSCALE; v.y *= QSCALE; v.z *= QSCALE; v.w *= QSCALE;
                const uint32_t h0 = pkh(v.x, v.y);
                const uint32_t h1 = pkh(v.z, v.w);
                *reinterpret_cast<uint2*>(&g_qh[o]) = make_uint2(h0, h1);
                *reinterpret_cast<uint2*>(&g_ql[o]) = make_uint2(
                    pkh(v.x - h_el0(h0), v.y - h_el1(h0)),
                    pkh(v.z - h_el0(h1), v.w - h_el1(h1)));
            } else if (slot == 1) {
                *reinterpret_cast<uint2*>(&g_k16[o]) =
                    make_uint2(pkh(v.x, v.y), pkh(v.z, v.w));
            } else {
                *reinterpret_cast<uint2*>(&g_v16[o]) =
                    make_uint2(pkh(v.x, v.y), pkh(v.z, v.w));
            }
        } else {
            *reinterpret_cast<float4*>(&out[(size_t)m * 1024 + n0 + c4]) = v;
        }
    }
}

// ---------------------------------------------------------------------------
// Flash attention, fp16 2-product scheme. CTA: 4 warps, 64 q-rows.
// Q = qh + ql (fp16), K,V single fp16; P split to ph + pl.
// Scores in log2 units (scale*log2e folded into Q at QKV epilogue).
// ---------------------------------------------------------------------------
#define AT_MAT 8192                       // 64 rows x 128B (swizzled)
#define AT_STG (2 * AT_MAT)               // K + V
#define ATTN_SMEM (2 * AT_MAT + 2 * AT_STG)  // Qh,Ql + 2 stages = 49152

__global__ __launch_bounds__(128)
void attn_kernel() {
    extern __shared__ char smem[];
    const uint32_t sb = smem_u32(smem);
    const int tid = threadIdx.x;
    const int lane = tid & 31;
    const int w = tid >> 5;
    const int qt = blockIdx.x;
    const int h  = blockIdx.y;
    const int b  = blockIdx.z;

    const size_t head_off = (size_t)(b * NHEAD + h) * TSEQ * HDIM;
    const size_t q_off = head_off + (size_t)qt * 64 * HDIM;

    const uint32_t sQh = sb;
    const uint32_t sQl = sb + AT_MAT;

    // Q tile hi+lo: 64 rows x 128B, rides in cp group 0.
    #pragma unroll
    for (int i = 0; i < 4; i++) {
        const int idx = tid + i * 128;     // 0..511
        const int r = idx >> 3;
        const int c = idx & 7;
        const uint32_t off = SWZ128((uint32_t)(r * 128 + c * 16));
        const size_t g = q_off + (size_t)r * HDIM + c * 8;
        cp16(sQh + off, g_qh + g);
        cp16(sQl + off, g_ql + g);
    }

    auto load_kv = [&](int kt, int stg) {
        const uint32_t base = sb + 2 * AT_MAT + stg * AT_STG;
        #pragma unroll
        for (int i = 0; i < 4; i++) {
            const int idx = tid + i * 128;
            const int r = idx >> 3;
            const int c = idx & 7;
            const uint32_t off = SWZ128((uint32_t)(r * 128 + c * 16));
            const size_t g = head_off + (size_t)(kt * 64 + r) * HDIM + c * 8;
            cp16(base + off, g_k16 + g);
            cp16(base + AT_MAT + off, g_v16 + g);
        }
        CP_COMMIT();
    };

    load_kv(0, 0);
    load_kv(1, 1);

    float o[8][4] = {};
    float m0r = -1e30f, m1r = -1e30f;
    float l0r = 0.0f, l1r = 0.0f;

    for (int kt = 0; kt < 32; kt++) {
        if (kt < 31) cp_wait<1>(); else cp_wait<0>();
        __syncthreads();
        const uint32_t kv = sb + 2 * AT_MAT + (kt & 1) * AT_STG;

        // ---- S = Q @ K^T (fp16 2-product) ----
        float s[8][4] = {};
        #pragma unroll
        for (int ks = 0; ks < 4; ks++) {
            const int cc = ks * 2 + (lane >> 4);
            uint32_t aqh[4], aql[4];
            const uint32_t qoff = SWZ128((uint32_t)((w * 16 + (lane & 15)) * 128 + cc * 16));
            ldsm_x4(aqh, sQh + qoff);
            ldsm_x4(aql, sQl + qoff);
            #pragma unroll
            for (int bp = 0; bp < 4; bp++) {
                uint32_t kh[4];
                const uint32_t koff = SWZ128((uint32_t)((bp * 16 + (lane & 15)) * 128 + cc * 16));
                ldsm_x4(kh, kv + koff);
                mma_fp16(s[2 * bp + 0], aqh, kh[0], kh[2]);
                mma_fp16(s[2 * bp + 0], aql, kh[0], kh[2]);
                mma_fp16(s[2 * bp + 1], aqh, kh[1], kh[3]);
                mma_fp16(s[2 * bp + 1], aql, kh[1], kh[3]);
            }
        }

        // ---- Online softmax on fragments ----
        float tm0 = -1e30f, tm1 = -1e30f;
        #pragma unroll
        for (int nt = 0; nt < 8; nt++) {
            tm0 = fmaxf(tm0, fmaxf(s[nt][0], s[nt][1]));
            tm1 = fmaxf(tm1, fmaxf(s[nt][2], s[nt][3]));
        }
        tm0 = fmaxf(tm0, __shfl_xor_sync(0xffffffffu, tm0, 1));
        tm0 = fmaxf(tm0, __shfl_xor_sync(0xffffffffu, tm0, 2));
        tm1 = fmaxf(tm1, __shfl_xor_sync(0xffffffffu, tm1, 1));
        tm1 = fmaxf(tm1, __shfl_xor_sync(0xffffffffu, tm1, 2));

        const float mn0 = fmaxf(m0r, tm0);
        const float mn1 = fmaxf(m1r, tm1);
        const float al0 = exp2f(m0r - mn0);
        const float al1 = exp2f(m1r - mn1);
        m0r = mn0; m1r = mn1;

        float sum0 = 0.0f, sum1 = 0.0f;
        uint32_t ph[8][2], pl[8][2];
        #pragma unroll
        for (int nt = 0; nt < 8; nt++) {
            const float p0 = exp2f(s[nt][0] - mn0);
            const float p1 = exp2f(s[nt][1] - mn0);
            const float p2 = exp2f(s[nt][2] - mn1);
            const float p3 = exp2f(s[nt][3] - mn1);
            sum0 += p0 + p1;
            sum1 += p2 + p3;
            ph[nt][0] = pkh(p0, p1);
            ph[nt][1] = pkh(p2, p3);
            pl[nt][0] = pkh(p0 - h_el0(ph[nt][0]), p1 - h_el1(ph[nt][0]));
            pl[nt][1] = pkh(p2 - h_el0(ph[nt][1]), p3 - h_el1(ph[nt][1]));
        }
        sum0 += __shfl_xor_sync(0xffffffffu, sum0, 1);
        sum0 += __shfl_xor_sync(0xffffffffu, sum0, 2);
        sum1 += __shfl_xor_sync(0xffffffffu, sum1, 1);
        sum1 += __shfl_xor_sync(0xffffffffu, sum1, 2);
        l0r = l0r * al0 + sum0;
        l1r = l1r * al1 + sum1;

        #pragma unroll
        for (int nt = 0; nt < 8; nt++) {
            o[nt][0] *= al0; o[nt][1] *= al0;
            o[nt][2] *= al1; o[nt][3] *= al1;
        }

        // ---- O += P @ V (fp16 2-product) ----
        #pragma unroll
        for (int j = 0; j < 4; j++) {
            uint32_t aPh[4] = { ph[2 * j][0], ph[2 * j][1],
                                ph[2 * j + 1][0], ph[2 * j + 1][1] };
            uint32_t aPl[4] = { pl[2 * j][0], pl[2 * j][1],
                                pl[2 * j + 1][0], pl[2 * j + 1][1] };
            #pragma unroll
            for (int dp = 0; dp < 4; dp++) {
                uint32_t vh[4];
                const int cc = dp * 2 + (lane >> 4);
                const uint32_t voff = SWZ128((uint32_t)((j * 16 + (lane & 15)) * 128 + cc * 16));
                ldsm_x4_t(vh, kv + AT_MAT + voff);
                mma_fp16(o[2 * dp + 0], aPh, vh[0], vh[1]);
                mma_fp16(o[2 * dp + 0], aPl, vh[0], vh[1]);
                mma_fp16(o[2 * dp + 1], aPh, vh[2], vh[3]);
                mma_fp16(o[2 * dp + 1], aPl, vh[2], vh[3]);
            }
        }
        __syncthreads();
        if (kt + 2 < 32) load_kv(kt + 2, kt & 1);
    }

    // ---- Normalize + write bf16 hi/lo to g_at [B,T,C] ----
    const float inv0 = 1.0f / l0r;
    const float inv1 = 1.0f / l1r;
    const int row0 = qt * 64 + w * 16 + (lane >> 2);
    #pragma unroll
    for (int nt = 0; nt < 8; nt++) {
        const int col = h * HDIM + nt * 8 + 2 * (lane & 3);
        const size_t o0 = ((size_t)b * TSEQ + row0) * CDIM + col;
        const size_t o1 = ((size_t)b * TSEQ + row0 + 8) * CDIM + col;
        const float v0 = o[nt][0] * inv0, v1 = o[nt][1] * inv0;
        const float v2 = o[nt][2] * inv1, v3 = o[nt][3] * inv1;
        const uint32_t h0 = pk(v0, v1);
        const uint32_t h1 = pk(v2, v3);
        *reinterpret_cast<uint32_t*>(&g_at_hi[o0]) = h0;
        *reinterpret_cast<uint32_t*>(&g_at_hi[o1]) = h1;
        *reinterpret_cast<uint32_t*>(&g_at_lo[o0]) =
            pk(v0 - bf_lo(h0), v1 - bf_hi(h0));
        *reinterpret_cast<uint32_t*>(&g_at_lo[o1]) =
            pk(v2 - bf_lo(h1), v3 - bf_hi(h1));
    }
}

// ---------------------------------------------------------------------------
// Launch
// ---------------------------------------------------------------------------
extern "C" void kernel_launch(void* const* d_in, const int* in_sizes, int n_in,
                              void* d_out, int out_size) {
    (void)in_sizes; (void)n_in; (void)out_size;
    const float* x      = (const float*)d_in[0];
    const float* w_qkv  = (const float*)d_in[1];
    const float* b_qkv  = (const float*)d_in[2];
    const float* w_proj = (const float*)d_in[3];
    const float* b_proj = (const float*)d_in[4];
    float* out = (float*)d_out;

    cudaFuncSetAttribute(mma_gemm<0>, cudaFuncAttributeMaxDynamicSharedMemorySize, GEMM_SMEM);
    cudaFuncSetAttribute(mma_gemm<1>, cudaFuncAttributeMaxDynamicSharedMemorySize, GEMM_SMEM);
    cudaFuncSetAttribute(attn_kernel, cudaFuncAttributeMaxDynamicSharedMemorySize, ATTN_SMEM);

    bf16 *x_hi, *x_lo, *wq_hi, *wq_lo, *wp_hi, *wp_lo, *at_hi, *at_lo;
    cudaGetSymbolAddress((void**)&x_hi,  g_x_hi);
    cudaGetSymbolAddress((void**)&x_lo,  g_x_lo);
    cudaGetSymbolAddress((void**)&wq_hi, g_wq_hi);
    cudaGetSymbolAddress((void**)&wq_lo, g_wq_lo);
    cudaGetSymbolAddress((void**)&wp_hi, g_wp_hi);
    cudaGetSymbolAddress((void**)&wp_lo, g_wp_lo);
    cudaGetSymbolAddress((void**)&at_hi, g_at_hi);
    cudaGetSymbolAddress((void**)&at_lo, g_at_lo);

    // Conversions
    split_kernel<<<4096, 256>>>(x, x_hi, x_lo, 4096 * 1024);
    transpose_split_kernel<<<dim3(96, 32), dim3(32, 8)>>>(w_qkv, wq_hi, wq_lo, 1024, 3072);
    transpose_split_kernel<<<dim3(32, 32), dim3(32, 8)>>>(w_proj, wp_hi, wp_lo, 1024, 1024);

    // QKV GEMM: M=4096, N=3072 -> grid (24, 32)
    mma_gemm<0><<<dim3(24, 32), 256, GEMM_SMEM>>>(x_hi, x_lo, wq_hi, wq_lo, b_qkv, nullptr);

    // Attention: (32 q-tiles, 16 heads, 2 batch)
    attn_kernel<<<dim3(32, NHEAD, BATCH), 128, ATTN_SMEM>>>();

    // Projection: M=4096, N=1024 -> grid (8, 32)
    mma_gemm<1><<<dim3(8, 32), 256, GEMM_SMEM>>>(at_hi, at_lo, wp_hi, wp_lo, b_proj, out);
}

// round 5
// speedup vs baseline: 4.9694x; 1.2438x over previous
#include <cuda_runtime.h>
#include <cuda_bf16.h>
#include <cuda_fp16.h>
#include <math.h>
#include <cstdint>

#define BATCH   2
#define TSEQ    2048
#define CDIM    1024
#define NHEAD   16
#define HDIM    64

typedef __half fp16;

// ---------------------------------------------------------------------------
// Scratch (__device__ globals; no allocation allowed)
// ---------------------------------------------------------------------------
#define QKV_ELEMS (BATCH * NHEAD * TSEQ * HDIM)
__device__ __align__(128) fp16 g_x_hi[4096 * 1024];
__device__ __align__(128) fp16 g_x_lo[4096 * 1024];
__device__ __align__(128) fp16 g_wq[3072 * 1024];      // transposed [N][K]
__device__ __align__(128) fp16 g_wp[1024 * 1024];      // transposed [N][K]
__device__ __align__(128) fp16 g_qh[QKV_ELEMS];        // q scaled, fp16 hi
__device__ __align__(128) fp16 g_ql[QKV_ELEMS];        // q scaled, fp16 lo
__device__ __align__(128) fp16 g_k16[QKV_ELEMS];       // k single fp16
__device__ __align__(128) fp16 g_v16[QKV_ELEMS];       // v single fp16
__device__ __align__(128) fp16 g_at_hi[4096 * 1024];   // attention out [B,T,C]
__device__ __align__(128) fp16 g_at_lo[4096 * 1024];

// ---------------------------------------------------------------------------
// Helpers
// ---------------------------------------------------------------------------
__device__ __forceinline__ uint32_t smem_u32(const void* p) {
    uint32_t a;
    asm("{ .reg .u64 t; cvta.to.shared.u64 t, %1; cvt.u32.u64 %0, t; }" : "=r"(a) : "l"(p));
    return a;
}

__device__ __forceinline__ void cp16(uint32_t dst, const void* src) {
    asm volatile("cp.async.cg.shared.global [%0], [%1], 16;" :: "r"(dst), "l"(src));
}
#define CP_COMMIT() asm volatile("cp.async.commit_group;" ::: "memory")
template <int N>
__device__ __forceinline__ void cp_wait() {
    asm volatile("cp.async.wait_group %0;" :: "n"(N) : "memory");
}

__device__ __forceinline__ void ldsm_x4(uint32_t* r, uint32_t addr) {
    asm volatile("ldmatrix.sync.aligned.m8n8.x4.shared.b16 {%0,%1,%2,%3}, [%4];"
                 : "=r"(r[0]), "=r"(r[1]), "=r"(r[2]), "=r"(r[3]) : "r"(addr));
}
__device__ __forceinline__ void ldsm_x4_t(uint32_t* r, uint32_t addr) {
    asm volatile("ldmatrix.sync.aligned.m8n8.x4.trans.shared.b16 {%0,%1,%2,%3}, [%4];"
                 : "=r"(r[0]), "=r"(r[1]), "=r"(r[2]), "=r"(r[3]) : "r"(addr));
}

// D += A * B, m16n8k16 fp16 -> f32
__device__ __forceinline__ void mma_fp16(float* c, const uint32_t* a,
                                         uint32_t b0, uint32_t b1) {
    asm volatile(
        "mma.sync.aligned.m16n8k16.row.col.f32.f16.f16.f32 "
        "{%0,%1,%2,%3}, {%4,%5,%6,%7}, {%8,%9}, {%0,%1,%2,%3};"
        : "+f"(c[0]), "+f"(c[1]), "+f"(c[2]), "+f"(c[3])
        : "r"(a[0]), "r"(a[1]), "r"(a[2]), "r"(a[3]), "r"(b0), "r"(b1));
}

// fp16 pack helpers
__device__ __forceinline__ uint32_t pkh(float a, float b) {
    __half2 h = __floats2half2_rn(a, b);
    return *reinterpret_cast<uint32_t*>(&h);
}
__device__ __forceinline__ float h_el0(uint32_t v) {
    return __half2float(__ushort_as_half((unsigned short)(v & 0xffffu)));
}
__device__ __forceinline__ float h_el1(uint32_t v) {
    return __half2float(__ushort_as_half((unsigned short)(v >> 16)));
}

// swizzles
#define SWZ128(off) ((off) ^ (((off) >> 3) & 0x70))
#define SWZ64(r, c) ((uint32_t)((r) * 64 + ((((c) ^ (((r) >> 1) & 3))) << 4)))

// ---------------------------------------------------------------------------
// Conversion kernels
// ---------------------------------------------------------------------------
__global__ __launch_bounds__(256)
void split_kernel(const float* __restrict__ src, fp16* __restrict__ hi,
                  fp16* __restrict__ lo, int n) {
    int i = (blockIdx.x * 256 + threadIdx.x) * 4;
    if (i >= n) return;
    float4 v = *reinterpret_cast<const float4*>(&src[i]);
    const uint32_t h0 = pkh(v.x, v.y);
    const uint32_t h1 = pkh(v.z, v.w);
    *reinterpret_cast<uint2*>(&hi[i]) = make_uint2(h0, h1);
    *reinterpret_cast<uint2*>(&lo[i]) = make_uint2(
        pkh(v.x - h_el0(h0), v.y - h_el1(h0)),
        pkh(v.z - h_el0(h1), v.w - h_el1(h1)));
}

// Transpose + convert: src f32 [K][N] -> fp16 [N][K]
__global__ __launch_bounds__(256)
void transpose_h_kernel(const float* __restrict__ src, fp16* __restrict__ dst,
                        int K, int N) {
    __shared__ float tile[32][33];
    const int bx = blockIdx.x * 32;
    const int by = blockIdx.y * 32;
    const int x = threadIdx.x;
    const int y = threadIdx.y;
    #pragma unroll
    for (int j = 0; j < 32; j += 8)
        tile[y + j][x] = src[(size_t)(by + y + j) * N + bx + x];
    __syncthreads();
    #pragma unroll
    for (int j = 0; j < 32; j += 8)
        dst[(size_t)(bx + y + j) * K + by + x] = __float2half(tile[x][y + j]);
}

// ---------------------------------------------------------------------------
// GEMM via mma.sync fp16x2: C[M,N] = (Ah+Al)[M,K=1024] @ B[N,K]^T + bias
// CTA 128x128, 8 warps (4x2), BK=32, 3-stage cp.async, swizzled 64B rows,
// 2 CTAs/SM. KIND 0: QKV scatter. KIND 1: f32 out.
// ---------------------------------------------------------------------------
#define GM_MAT 8192                    // 128 rows * 64B
#define GM_STG (3 * GM_MAT)            // 24576 (Ah, Al, B)
#define GM_STAGES 3
#define GEMM_SMEM (GM_STAGES * GM_STG) // 73728 (epilogue needs 67.6KB, fits)

#define QSCALE 0.1803368801111f        // 0.125 * log2(e)

template <int KIND>
__global__ __launch_bounds__(256, 2)
void mma_gemm(const fp16* __restrict__ a_hi, const fp16* __restrict__ a_lo,
              const fp16* __restrict__ bmat,
              const float* __restrict__ bias, float* __restrict__ out) {
    extern __shared__ char smem[];
    const uint32_t sb = smem_u32(smem);
    const int tid = threadIdx.x;
    const int lane = tid & 31;
    const int wid = tid >> 5;
    const int wm = wid & 3;
    const int wn = wid >> 2;
    const int n0 = blockIdx.x * 128;
    const int m0 = blockIdx.y * 128;
    const int NCH = 32;

    auto load_chunk = [&](int ch, int stg) {
        const uint32_t base = sb + stg * GM_STG;
        const int k0 = ch * 32;
        #pragma unroll
        for (int i = 0; i < 2; i++) {
            const int idx = tid + i * 256;     // 0..511
            const int r = idx >> 2;            // 0..127
            const int c = idx & 3;             // 16B chunk within 64B row
            const uint32_t off = SWZ64(r, c);
            const size_t ga = (size_t)(m0 + r) * 1024 + k0 + c * 8;
            const size_t gb = (size_t)(n0 + r) * 1024 + k0 + c * 8;
            cp16(base + 0 * GM_MAT + off, a_hi + ga);
            cp16(base + 1 * GM_MAT + off, a_lo + ga);
            cp16(base + 2 * GM_MAT + off, bmat + gb);
        }
        CP_COMMIT();
    };

    float acc[2][8][4] = {};
    load_chunk(0, 0);
    load_chunk(1, 1);

    for (int ch = 0; ch < NCH; ch++) {
        if (ch < NCH - 1) cp_wait<1>(); else cp_wait<0>();
        __syncthreads();
        if (ch + 2 < NCH) load_chunk(ch + 2, (ch + 2) % GM_STAGES);

        const uint32_t base = sb + (ch % GM_STAGES) * GM_STG;
        #pragma unroll
        for (int ks = 0; ks < 2; ks++) {
            const int cc = ks * 2 + (lane >> 4);
            uint32_t ah[2][4], al[2][4];
            #pragma unroll
            for (int mt = 0; mt < 2; mt++) {
                const int row = wm * 32 + mt * 16 + (lane & 15);
                const uint32_t addr = base + SWZ64(row, cc);
                ldsm_x4(ah[mt], addr);
                ldsm_x4(al[mt], addr + GM_MAT);
            }
            #pragma unroll
            for (int bp = 0; bp < 4; bp++) {
                uint32_t bh[4];
                const int row = wn * 64 + bp * 16 + (lane & 15);
                ldsm_x4(bh, base + 2 * GM_MAT + SWZ64(row, cc));
                #pragma unroll
                for (int mt = 0; mt < 2; mt++) {
                    mma_fp16(acc[mt][2 * bp + 0], ah[mt], bh[0], bh[2]);
                    mma_fp16(acc[mt][2 * bp + 0], al[mt], bh[0], bh[2]);
                    mma_fp16(acc[mt][2 * bp + 1], ah[mt], bh[1], bh[3]);
                    mma_fp16(acc[mt][2 * bp + 1], al[mt], bh[1], bh[3]);
                }
            }
        }
    }
    __syncthreads();   // mainloop smem reads done before epilogue overwrite

    // Epilogue: stage fp32 C in smem, then coalesced writes.
    float* sC = reinterpret_cast<float*>(smem);   // [128][132]
    #pragma unroll
    for (int mt = 0; mt < 2; mt++)
        #pragma unroll
        for (int nt = 0; nt < 8; nt++) {
            const int r = wm * 32 + mt * 16 + (lane >> 2);
            const int c = wn * 64 + nt * 8 + 2 * (lane & 3);
            sC[r * 132 + c]           = acc[mt][nt][0];
            sC[r * 132 + c + 1]       = acc[mt][nt][1];
            sC[(r + 8) * 132 + c]     = acc[mt][nt][2];
            sC[(r + 8) * 132 + c + 1] = acc[mt][nt][3];
        }
    __syncthreads();

    #pragma unroll
    for (int it = 0; it < 16; it++) {
        const int idx = tid + it * 256;     // 0..4095
        const int r = idx >> 5;
        const int c4 = (idx & 31) * 4;
        float4 v = *reinterpret_cast<float4*>(&sC[r * 132 + c4]);
        const float4 bb = *reinterpret_cast<const float4*>(&bias[n0 + c4]);
        v.x += bb.x; v.y += bb.y; v.z += bb.z; v.w += bb.w;
        const int m = m0 + r;
        if (KIND == 0) {
            const int n = n0 + c4;
            const int slot = n >> 10;
            const int h = (n >> 6) & 15;
            const int d = n & 63;
            const int b = m >> 11;
            const int t = m & 2047;
            const size_t o = ((size_t)(b * NHEAD + h) * TSEQ + t) * HDIM + d;
            if (slot == 0) {
                v.x *= QSCALE; v.y *= QSCALE; v.z *= QSCALE; v.w *= QSCALE;
                const uint32_t h0 = pkh(v.x, v.y);
                const uint32_t h1 = pkh(v.z, v.w);
                *reinterpret_cast<uint2*>(&g_qh[o]) = make_uint2(h0, h1);
                *reinterpret_cast<uint2*>(&g_ql[o]) = make_uint2(
                    pkh(v.x - h_el0(h0), v.y - h_el1(h0)),
                    pkh(v.z - h_el0(h1), v.w - h_el1(h1)));
            } else if (slot == 1) {
                *reinterpret_cast<uint2*>(&g_k16[o]) =
                    make_uint2(pkh(v.x, v.y), pkh(v.z, v.w));
            } else {
                *reinterpret_cast<uint2*>(&g_v16[o]) =
                    make_uint2(pkh(v.x, v.y), pkh(v.z, v.w));
            }
        } else {
            *reinterpret_cast<float4*>(&out[(size_t)m * 1024 + n0 + c4]) = v;
        }
    }
}

// ---------------------------------------------------------------------------
// Flash attention, fp16 2-product scheme. CTA: 4 warps, 64 q-rows.
// Q = qh + ql (fp16), K,V single fp16; P split to ph + pl.
// Scores in log2 units (scale*log2e folded into Q at QKV epilogue).
// ---------------------------------------------------------------------------
#define AT_MAT 8192                       // 64 rows x 128B (swizzled)
#define AT_STG (2 * AT_MAT)               // K + V
#define ATTN_SMEM (2 * AT_MAT + 2 * AT_STG)  // Qh,Ql + 2 stages = 49152

__global__ __launch_bounds__(128)
void attn_kernel() {
    extern __shared__ char smem[];
    const uint32_t sb = smem_u32(smem);
    const int tid = threadIdx.x;
    const int lane = tid & 31;
    const int w = tid >> 5;
    const int qt = blockIdx.x;
    const int h  = blockIdx.y;
    const int b  = blockIdx.z;

    const size_t head_off = (size_t)(b * NHEAD + h) * TSEQ * HDIM;
    const size_t q_off = head_off + (size_t)qt * 64 * HDIM;

    const uint32_t sQh = sb;
    const uint32_t sQl = sb + AT_MAT;

    // Q tile hi+lo: 64 rows x 128B, rides in cp group 0.
    #pragma unroll
    for (int i = 0; i < 4; i++) {
        const int idx = tid + i * 128;     // 0..511
        const int r = idx >> 3;
        const int c = idx & 7;
        const uint32_t off = SWZ128((uint32_t)(r * 128 + c * 16));
        const size_t g = q_off + (size_t)r * HDIM + c * 8;
        cp16(sQh + off, g_qh + g);
        cp16(sQl + off, g_ql + g);
    }

    auto load_kv = [&](int kt, int stg) {
        const uint32_t base = sb + 2 * AT_MAT + stg * AT_STG;
        #pragma unroll
        for (int i = 0; i < 4; i++) {
            const int idx = tid + i * 128;
            const int r = idx >> 3;
            const int c = idx & 7;
            const uint32_t off = SWZ128((uint32_t)(r * 128 + c * 16));
            const size_t g = head_off + (size_t)(kt * 64 + r) * HDIM + c * 8;
            cp16(base + off, g_k16 + g);
            cp16(base + AT_MAT + off, g_v16 + g);
        }
        CP_COMMIT();
    };

    load_kv(0, 0);
    load_kv(1, 1);

    float o[8][4] = {};
    float m0r = -1e30f, m1r = -1e30f;
    float l0r = 0.0f, l1r = 0.0f;

    for (int kt = 0; kt < 32; kt++) {
        if (kt < 31) cp_wait<1>(); else cp_wait<0>();
        __syncthreads();
        const uint32_t kv = sb + 2 * AT_MAT + (kt & 1) * AT_STG;

        // ---- S = Q @ K^T (fp16 2-product) ----
        float s[8][4] = {};
        #pragma unroll
        for (int ks = 0; ks < 4; ks++) {
            const int cc = ks * 2 + (lane >> 4);
            uint32_t aqh[4], aql[4];
            const uint32_t qoff = SWZ128((uint32_t)((w * 16 + (lane & 15)) * 128 + cc * 16));
            ldsm_x4(aqh, sQh + qoff);
            ldsm_x4(aql, sQl + qoff);
            #pragma unroll
            for (int bp = 0; bp < 4; bp++) {
                uint32_t kh[4];
                const uint32_t koff = SWZ128((uint32_t)((bp * 16 + (lane & 15)) * 128 + cc * 16));
                ldsm_x4(kh, kv + koff);
                mma_fp16(s[2 * bp + 0], aqh, kh[0], kh[2]);
                mma_fp16(s[2 * bp + 0], aql, kh[0], kh[2]);
                mma_fp16(s[2 * bp + 1], aqh, kh[1], kh[3]);
                mma_fp16(s[2 * bp + 1], aql, kh[1], kh[3]);
            }
        }

        // ---- Online softmax on fragments ----
        float tm0 = -1e30f, tm1 = -1e30f;
        #pragma unroll
        for (int nt = 0; nt < 8; nt++) {
            tm0 = fmaxf(tm0, fmaxf(s[nt][0], s[nt][1]));
            tm1 = fmaxf(tm1, fmaxf(s[nt][2], s[nt][3]));
        }
        tm0 = fmaxf(tm0, __shfl_xor_sync(0xffffffffu, tm0, 1));
        tm0 = fmaxf(tm0, __shfl_xor_sync(0xffffffffu, tm0, 2));
        tm1 = fmaxf(tm1, __shfl_xor_sync(0xffffffffu, tm1, 1));
        tm1 = fmaxf(tm1, __shfl_xor_sync(0xffffffffu, tm1, 2));

        const float mn0 = fmaxf(m0r, tm0);
        const float mn1 = fmaxf(m1r, tm1);
        const float al0 = exp2f(m0r - mn0);
        const float al1 = exp2f(m1r - mn1);
        m0r = mn0; m1r = mn1;

        float sum0 = 0.0f, sum1 = 0.0f;
        uint32_t ph[8][2], pl[8][2];
        #pragma unroll
        for (int nt = 0; nt < 8; nt++) {
            const float p0 = exp2f(s[nt][0] - mn0);
            const float p1 = exp2f(s[nt][1] - mn0);
            const float p2 = exp2f(s[nt][2] - mn1);
            const float p3 = exp2f(s[nt][3] - mn1);
            sum0 += p0 + p1;
            sum1 += p2 + p3;
            ph[nt][0] = pkh(p0, p1);
            ph[nt][1] = pkh(p2, p3);
            pl[nt][0] = pkh(p0 - h_el0(ph[nt][0]), p1 - h_el1(ph[nt][0]));
            pl[nt][1] = pkh(p2 - h_el0(ph[nt][1]), p3 - h_el1(ph[nt][1]));
        }
        sum0 += __shfl_xor_sync(0xffffffffu, sum0, 1);
        sum0 += __shfl_xor_sync(0xffffffffu, sum0, 2);
        sum1 += __shfl_xor_sync(0xffffffffu, sum1, 1);
        sum1 += __shfl_xor_sync(0xffffffffu, sum1, 2);
        l0r = l0r * al0 + sum0;
        l1r = l1r * al1 + sum1;

        #pragma unroll
        for (int nt = 0; nt < 8; nt++) {
            o[nt][0] *= al0; o[nt][1] *= al0;
            o[nt][2] *= al1; o[nt][3] *= al1;
        }

        // ---- O += P @ V (fp16 2-product) ----
        #pragma unroll
        for (int j = 0; j < 4; j++) {
            uint32_t aPh[4] = { ph[2 * j][0], ph[2 * j][1],
                                ph[2 * j + 1][0], ph[2 * j + 1][1] };
            uint32_t aPl[4] = { pl[2 * j][0], pl[2 * j][1],
                                pl[2 * j + 1][0], pl[2 * j + 1][1] };
            #pragma unroll
            for (int dp = 0; dp < 4; dp++) {
                uint32_t vh[4];
                const int cc = dp * 2 + (lane >> 4);
                const uint32_t voff = SWZ128((uint32_t)((j * 16 + (lane & 15)) * 128 + cc * 16));
                ldsm_x4_t(vh, kv + AT_MAT + voff);
                mma_fp16(o[2 * dp + 0], aPh, vh[0], vh[1]);
                mma_fp16(o[2 * dp + 0], aPl, vh[0], vh[1]);
                mma_fp16(o[2 * dp + 1], aPh, vh[2], vh[3]);
                mma_fp16(o[2 * dp + 1], aPl, vh[2], vh[3]);
            }
        }
        __syncthreads();
        if (kt + 2 < 32) load_kv(kt + 2, kt & 1);
    }

    // ---- Normalize + write fp16 hi/lo to g_at [B,T,C] ----
    const float inv0 = 1.0f / l0r;
    const float inv1 = 1.0f / l1r;
    const int row0 = qt * 64 + w * 16 + (lane >> 2);
    #pragma unroll
    for (int nt = 0; nt < 8; nt++) {
        const int col = h * HDIM + nt * 8 + 2 * (lane & 3);
        const size_t o0 = ((size_t)b * TSEQ + row0) * CDIM + col;
        const size_t o1 = ((size_t)b * TSEQ + row0 + 8) * CDIM + col;
        const float v0 = o[nt][0] * inv0, v1 = o[nt][1] * inv0;
        const float v2 = o[nt][2] * inv1, v3 = o[nt][3] * inv1;
        const uint32_t h0 = pkh(v0, v1);
        const uint32_t h1 = pkh(v2, v3);
        *reinterpret_cast<uint32_t*>(&g_at_hi[o0]) = h0;
        *reinterpret_cast<uint32_t*>(&g_at_hi[o1]) = h1;
        *reinterpret_cast<uint32_t*>(&g_at_lo[o0]) =
            pkh(v0 - h_el0(h0), v1 - h_el1(h0));
        *reinterpret_cast<uint32_t*>(&g_at_lo[o1]) =
            pkh(v2 - h_el0(h1), v3 - h_el1(h1));
    }
}

// ---------------------------------------------------------------------------
// Launch
// ---------------------------------------------------------------------------
extern "C" void kernel_launch(void* const* d_in, const int* in_sizes, int n_in,
                              void* d_out, int out_size) {
    (void)in_sizes; (void)n_in; (void)out_size;
    const float* x      = (const float*)d_in[0];
    const float* w_qkv  = (const float*)d_in[1];
    const float* b_qkv  = (const float*)d_in[2];
    const float* w_proj = (const float*)d_in[3];
    const float* b_proj = (const float*)d_in[4];
    float* out = (float*)d_out;

    cudaFuncSetAttribute(mma_gemm<0>, cudaFuncAttributeMaxDynamicSharedMemorySize, GEMM_SMEM);
    cudaFuncSetAttribute(mma_gemm<1>, cudaFuncAttributeMaxDynamicSharedMemorySize, GEMM_SMEM);
    cudaFuncSetAttribute(attn_kernel, cudaFuncAttributeMaxDynamicSharedMemorySize, ATTN_SMEM);

    fp16 *x_hi, *x_lo, *wq, *wp, *at_hi, *at_lo;
    cudaGetSymbolAddress((void**)&x_hi,  g_x_hi);
    cudaGetSymbolAddress((void**)&x_lo,  g_x_lo);
    cudaGetSymbolAddress((void**)&wq,    g_wq);
    cudaGetSymbolAddress((void**)&wp,    g_wp);
    cudaGetSymbolAddress((void**)&at_hi, g_at_hi);
    cudaGetSymbolAddress((void**)&at_lo, g_at_lo);

    // Conversions
    split_kernel<<<4096, 256>>>(x, x_hi, x_lo, 4096 * 1024);
    transpose_h_kernel<<<dim3(96, 32), dim3(32, 8)>>>(w_qkv, wq, 1024, 3072);
    transpose_h_kernel<<<dim3(32, 32), dim3(32, 8)>>>(w_proj, wp, 1024, 1024);

    // QKV GEMM: M=4096, N=3072 -> grid (24, 32)
    mma_gemm<0><<<dim3(24, 32), 256, GEMM_SMEM>>>(x_hi, x_lo, wq, b_qkv, nullptr);

    // Attention: (32 q-tiles, 16 heads, 2 batch)
    attn_kernel<<<dim3(32, NHEAD, BATCH), 128, ATTN_SMEM>>>();

    // Projection: M=4096, N=1024 -> grid (8, 32)
    mma_gemm<1><<<dim3(8, 32), 256, GEMM_SMEM>>>(at_hi, at_lo, wp, b_proj, out);
}

// round 6
// speedup vs baseline: 5.8730x; 1.1818x over previous
#include <cuda_runtime.h>
#include <cuda_bf16.h>
#include <cuda_fp16.h>
#include <math.h>
#include <cstdint>

#define BATCH   2
#define TSEQ    2048
#define CDIM    1024
#define NHEAD   16
#define HDIM    64

typedef __half fp16;

// ---------------------------------------------------------------------------
// Scratch (__device__ globals; no allocation allowed)
// ---------------------------------------------------------------------------
#define QKV_ELEMS (BATCH * NHEAD * TSEQ * HDIM)
__device__ __align__(128) fp16 g_x_hi[4096 * 1024];
__device__ __align__(128) fp16 g_x_lo[4096 * 1024];
__device__ __align__(128) fp16 g_wq[3072 * 1024];      // transposed [N][K]
__device__ __align__(128) fp16 g_wp[1024 * 1024];      // transposed [N][K]
__device__ __align__(128) fp16 g_qh[QKV_ELEMS];        // q scaled, fp16 hi
__device__ __align__(128) fp16 g_ql[QKV_ELEMS];        // q scaled, fp16 lo
__device__ __align__(128) fp16 g_k16[QKV_ELEMS];       // k single fp16
__device__ __align__(128) fp16 g_v16[QKV_ELEMS];       // v single fp16
__device__ __align__(128) fp16 g_at_hi[4096 * 1024];   // attention out [B,T,C]
__device__ __align__(128) fp16 g_at_lo[4096 * 1024];

// ---------------------------------------------------------------------------
// Helpers
// ---------------------------------------------------------------------------
__device__ __forceinline__ uint32_t smem_u32(const void* p) {
    uint32_t a;
    asm("{ .reg .u64 t; cvta.to.shared.u64 t, %1; cvt.u32.u64 %0, t; }" : "=r"(a) : "l"(p));
    return a;
}

__device__ __forceinline__ void cp16(uint32_t dst, const void* src) {
    asm volatile("cp.async.cg.shared.global [%0], [%1], 16;" :: "r"(dst), "l"(src));
}
#define CP_COMMIT() asm volatile("cp.async.commit_group;" ::: "memory")
template <int N>
__device__ __forceinline__ void cp_wait() {
    asm volatile("cp.async.wait_group %0;" :: "n"(N) : "memory");
}

__device__ __forceinline__ void ldsm_x4(uint32_t* r, uint32_t addr) {
    asm volatile("ldmatrix.sync.aligned.m8n8.x4.shared.b16 {%0,%1,%2,%3}, [%4];"
                 : "=r"(r[0]), "=r"(r[1]), "=r"(r[2]), "=r"(r[3]) : "r"(addr));
}
__device__ __forceinline__ void ldsm_x4_t(uint32_t* r, uint32_t addr) {
    asm volatile("ldmatrix.sync.aligned.m8n8.x4.trans.shared.b16 {%0,%1,%2,%3}, [%4];"
                 : "=r"(r[0]), "=r"(r[1]), "=r"(r[2]), "=r"(r[3]) : "r"(addr));
}

// D += A * B, m16n8k16 fp16 -> f32
__device__ __forceinline__ void mma_fp16(float* c, const uint32_t* a,
                                         uint32_t b0, uint32_t b1) {
    asm volatile(
        "mma.sync.aligned.m16n8k16.row.col.f32.f16.f16.f32 "
        "{%0,%1,%2,%3}, {%4,%5,%6,%7}, {%8,%9}, {%0,%1,%2,%3};"
        : "+f"(c[0]), "+f"(c[1]), "+f"(c[2]), "+f"(c[3])
        : "r"(a[0]), "r"(a[1]), "r"(a[2]), "r"(a[3]), "r"(b0), "r"(b1));
}

// fp16 pack helpers
__device__ __forceinline__ uint32_t pkh(float a, float b) {
    __half2 h = __floats2half2_rn(a, b);
    return *reinterpret_cast<uint32_t*>(&h);
}
__device__ __forceinline__ float h_el0(uint32_t v) {
    return __half2float(__ushort_as_half((unsigned short)(v & 0xffffu)));
}
__device__ __forceinline__ float h_el1(uint32_t v) {
    return __half2float(__ushort_as_half((unsigned short)(v >> 16)));
}

__device__ __forceinline__ float ex2(float x) {
    float y;
    asm("ex2.approx.ftz.f32 %0, %1;" : "=f"(y) : "f"(x));
    return y;
}

// swizzle for 128B rows
#define SWZ128(off) ((uint32_t)(off) ^ ((((uint32_t)(off)) >> 3) & 0x70))

// ---------------------------------------------------------------------------
// Conversion kernels
// ---------------------------------------------------------------------------
__global__ __launch_bounds__(256)
void split_kernel(const float* __restrict__ src, fp16* __restrict__ hi,
                  fp16* __restrict__ lo, int n) {
    int i = (blockIdx.x * 256 + threadIdx.x) * 4;
    if (i >= n) return;
    float4 v = *reinterpret_cast<const float4*>(&src[i]);
    const uint32_t h0 = pkh(v.x, v.y);
    const uint32_t h1 = pkh(v.z, v.w);
    *reinterpret_cast<uint2*>(&hi[i]) = make_uint2(h0, h1);
    *reinterpret_cast<uint2*>(&lo[i]) = make_uint2(
        pkh(v.x - h_el0(h0), v.y - h_el1(h0)),
        pkh(v.z - h_el0(h1), v.w - h_el1(h1)));
}

// Transpose + convert: src f32 [K][N] -> fp16 [N][K]
__global__ __launch_bounds__(256)
void transpose_h_kernel(const float* __restrict__ src, fp16* __restrict__ dst,
                        int K, int N) {
    __shared__ float tile[32][33];
    const int bx = blockIdx.x * 32;
    const int by = blockIdx.y * 32;
    const int x = threadIdx.x;
    const int y = threadIdx.y;
    #pragma unroll
    for (int j = 0; j < 32; j += 8)
        tile[y + j][x] = src[(size_t)(by + y + j) * N + bx + x];
    __syncthreads();
    #pragma unroll
    for (int j = 0; j < 32; j += 8)
        dst[(size_t)(bx + y + j) * K + by + x] = __float2half(tile[x][y + j]);
}

// ---------------------------------------------------------------------------
// GEMM via mma.sync fp16x2: C[M,N] = (Ah+Al)[M,K=1024] @ B[N,K]^T + bias
// CTA 128x128, 8 warps (4x2), BK=64, 2-stage cp.async, SW128 rows,
// ONE __syncthreads per chunk, 2 CTAs/SM.
// KIND 0: QKV scatter. KIND 1: f32 out.
// ---------------------------------------------------------------------------
#define GM_MAT 16384                   // 128 rows * 128B
#define GM_STG (3 * GM_MAT)            // 49152 (Ah, Al, B)
#define GEMM_SMEM (2 * GM_STG)         // 98304 (epilogue needs 67.6KB, fits)

#define QSCALE 0.1803368801111f        // 0.125 * log2(e)

template <int KIND>
__global__ __launch_bounds__(256, 2)
void mma_gemm(const fp16* __restrict__ a_hi, const fp16* __restrict__ a_lo,
              const fp16* __restrict__ bmat,
              const float* __restrict__ bias, float* __restrict__ out) {
    extern __shared__ char smem[];
    const uint32_t sb = smem_u32(smem);
    const int tid = threadIdx.x;
    const int lane = tid & 31;
    const int wid = tid >> 5;
    const int wm = wid & 3;
    const int wn = wid >> 2;
    const int n0 = blockIdx.x * 128;
    const int m0 = blockIdx.y * 128;
    const int NCH = 16;                // K=1024 / 64

    auto load_chunk = [&](int ch) {
        const uint32_t base = sb + (ch & 1) * GM_STG;
        const int k0 = ch * 64;
        #pragma unroll
        for (int i = 0; i < 4; i++) {
            const int idx = tid + i * 256;     // 0..1023
            const int r = idx >> 3;            // 0..127
            const int c = idx & 7;             // 16B chunk within 128B row
            const uint32_t off = SWZ128(r * 128 + c * 16);
            const size_t ga = (size_t)(m0 + r) * 1024 + k0 + c * 8;
            const size_t gb = (size_t)(n0 + r) * 1024 + k0 + c * 8;
            cp16(base + 0 * GM_MAT + off, a_hi + ga);
            cp16(base + 1 * GM_MAT + off, a_lo + ga);
            cp16(base + 2 * GM_MAT + off, bmat + gb);
        }
        CP_COMMIT();
    };

    float acc[2][8][4] = {};
    load_chunk(0);

    for (int ch = 0; ch < NCH; ch++) {
        cp_wait<0>();
        __syncthreads();               // data visible + prev compute complete
        if (ch + 1 < NCH) load_chunk(ch + 1);

        const uint32_t base = sb + (ch & 1) * GM_STG;
        #pragma unroll
        for (int ks = 0; ks < 4; ks++) {
            const int cc = ks * 2 + (lane >> 4);
            uint32_t ah[2][4], al[2][4];
            #pragma unroll
            for (int mt = 0; mt < 2; mt++) {
                const int row = wm * 32 + mt * 16 + (lane & 15);
                const uint32_t addr = base + SWZ128(row * 128 + cc * 16);
                ldsm_x4(ah[mt], addr);
                ldsm_x4(al[mt], addr + GM_MAT);
            }
            #pragma unroll
            for (int bp = 0; bp < 4; bp++) {
                uint32_t bh[4];
                const int row = wn * 64 + bp * 16 + (lane & 15);
                ldsm_x4(bh, base + 2 * GM_MAT + SWZ128(row * 128 + cc * 16));
                #pragma unroll
                for (int mt = 0; mt < 2; mt++) {
                    mma_fp16(acc[mt][2 * bp + 0], ah[mt], bh[0], bh[2]);
                    mma_fp16(acc[mt][2 * bp + 0], al[mt], bh[0], bh[2]);
                    mma_fp16(acc[mt][2 * bp + 1], ah[mt], bh[1], bh[3]);
                    mma_fp16(acc[mt][2 * bp + 1], al[mt], bh[1], bh[3]);
                }
            }
        }
    }
    __syncthreads();   // mainloop smem reads done before epilogue overwrite

    // Epilogue: stage fp32 C in smem, then coalesced writes.
    float* sC = reinterpret_cast<float*>(smem);   // [128][132]
    #pragma unroll
    for (int mt = 0; mt < 2; mt++)
        #pragma unroll
        for (int nt = 0; nt < 8; nt++) {
            const int r = wm * 32 + mt * 16 + (lane >> 2);
            const int c = wn * 64 + nt * 8 + 2 * (lane & 3);
            sC[r * 132 + c]           = acc[mt][nt][0];
            sC[r * 132 + c + 1]       = acc[mt][nt][1];
            sC[(r + 8) * 132 + c]     = acc[mt][nt][2];
            sC[(r + 8) * 132 + c + 1] = acc[mt][nt][3];
        }
    __syncthreads();

    #pragma unroll
    for (int it = 0; it < 16; it++) {
        const int idx = tid + it * 256;     // 0..4095
        const int r = idx >> 5;
        const int c4 = (idx & 31) * 4;
        float4 v = *reinterpret_cast<float4*>(&sC[r * 132 + c4]);
        const float4 bb = *reinterpret_cast<const float4*>(&bias[n0 + c4]);
        v.x += bb.x; v.y += bb.y; v.z += bb.z; v.w += bb.w;
        const int m = m0 + r;
        if (KIND == 0) {
            const int n = n0 + c4;
            const int slot = n >> 10;
            const int h = (n >> 6) & 15;
            const int d = n & 63;
            const int b = m >> 11;
            const int t = m & 2047;
            const size_t o = ((size_t)(b * NHEAD + h) * TSEQ + t) * HDIM + d;
            if (slot == 0) {
                v.x *= QSCALE; v.y *= QSCALE; v.z *= QSCALE; v.w *= QSCALE;
                const uint32_t h0 = pkh(v.x, v.y);
                const uint32_t h1 = pkh(v.z, v.w);
                *reinterpret_cast<uint2*>(&g_qh[o]) = make_uint2(h0, h1);
                *reinterpret_cast<uint2*>(&g_ql[o]) = make_uint2(
                    pkh(v.x - h_el0(h0), v.y - h_el1(h0)),
                    pkh(v.z - h_el0(h1), v.w - h_el1(h1)));
            } else if (slot == 1) {
                *reinterpret_cast<uint2*>(&g_k16[o]) =
                    make_uint2(pkh(v.x, v.y), pkh(v.z, v.w));
            } else {
                *reinterpret_cast<uint2*>(&g_v16[o]) =
                    make_uint2(pkh(v.x, v.y), pkh(v.z, v.w));
            }
        } else {
            *reinterpret_cast<float4*>(&out[(size_t)m * 1024 + n0 + c4]) = v;
        }
    }
}

// ---------------------------------------------------------------------------
// Flash attention. CTA: 4 warps, 64 q-rows.
// QK^T: (Qh+Ql) @ K16 (2-product). P@V: Ph @ V16 (1-product; V already
// rounded at source so P-lo is subdominant).
// Scores in log2 units (scale*log2e folded into Q at QKV epilogue).
// One barrier per kt iteration.
// ---------------------------------------------------------------------------
#define AT_MAT 8192                       // 64 rows x 128B (swizzled)
#define AT_STG (2 * AT_MAT)               // K + V
#define ATTN_SMEM (2 * AT_MAT + 2 * AT_STG)  // Qh,Ql + 2 stages = 49152

__global__ __launch_bounds__(128)
void attn_kernel() {
    extern __shared__ char smem[];
    const uint32_t sb = smem_u32(smem);
    const int tid = threadIdx.x;
    const int lane = tid & 31;
    const int w = tid >> 5;
    const int qt = blockIdx.x;
    const int h  = blockIdx.y;
    const int b  = blockIdx.z;

    const size_t head_off = (size_t)(b * NHEAD + h) * TSEQ * HDIM;
    const size_t q_off = head_off + (size_t)qt * 64 * HDIM;

    const uint32_t sQh = sb;
    const uint32_t sQl = sb + AT_MAT;

    auto load_kv = [&](int kt) {
        const uint32_t base = sb + 2 * AT_MAT + (kt & 1) * AT_STG;
        #pragma unroll
        for (int i = 0; i < 4; i++) {
            const int idx = tid + i * 128;
            const int r = idx >> 3;
            const int c = idx & 7;
            const uint32_t off = SWZ128(r * 128 + c * 16);
            const size_t g = head_off + (size_t)(kt * 64 + r) * HDIM + c * 8;
            cp16(base + off, g_k16 + g);
            cp16(base + AT_MAT + off, g_v16 + g);
        }
        CP_COMMIT();
    };

    // Q tile hi+lo rides with KV(0) in one group.
    #pragma unroll
    for (int i = 0; i < 4; i++) {
        const int idx = tid + i * 128;     // 0..511
        const int r = idx >> 3;
        const int c = idx & 7;
        const uint32_t off = SWZ128(r * 128 + c * 16);
        const size_t g = q_off + (size_t)r * HDIM + c * 8;
        cp16(sQh + off, g_qh + g);
        cp16(sQl + off, g_ql + g);
    }
    load_kv(0);

    float o[8][4] = {};
    float m0r = -1e30f, m1r = -1e30f;
    float l0r = 0.0f, l1r = 0.0f;

    for (int kt = 0; kt < 32; kt++) {
        cp_wait<0>();
        __syncthreads();               // data in + all warps done with other stage
        if (kt + 1 < 32) load_kv(kt + 1);
        const uint32_t kv = sb + 2 * AT_MAT + (kt & 1) * AT_STG;

        // ---- S = Q @ K^T (fp16 2-product) ----
        float s[8][4] = {};
        #pragma unroll
        for (int ks = 0; ks < 4; ks++) {
            const int cc = ks * 2 + (lane >> 4);
            uint32_t aqh[4], aql[4];
            const uint32_t qoff = SWZ128((w * 16 + (lane & 15)) * 128 + cc * 16);
            ldsm_x4(aqh, sQh + qoff);
            ldsm_x4(aql, sQl + qoff);
            #pragma unroll
            for (int bp = 0; bp < 4; bp++) {
                uint32_t kh[4];
                const uint32_t koff = SWZ128((bp * 16 + (lane & 15)) * 128 + cc * 16);
                ldsm_x4(kh, kv + koff);
                mma_fp16(s[2 * bp + 0], aqh, kh[0], kh[2]);
                mma_fp16(s[2 * bp + 0], aql, kh[0], kh[2]);
                mma_fp16(s[2 * bp + 1], aqh, kh[1], kh[3]);
                mma_fp16(s[2 * bp + 1], aql, kh[1], kh[3]);
            }
        }

        // ---- Online softmax on fragments ----
        float tm0 = -1e30f, tm1 = -1e30f;
        #pragma unroll
        for (int nt = 0; nt < 8; nt++) {
            tm0 = fmaxf(tm0, fmaxf(s[nt][0], s[nt][1]));
            tm1 = fmaxf(tm1, fmaxf(s[nt][2], s[nt][3]));
        }
        tm0 = fmaxf(tm0, __shfl_xor_sync(0xffffffffu, tm0, 1));
        tm0 = fmaxf(tm0, __shfl_xor_sync(0xffffffffu, tm0, 2));
        tm1 = fmaxf(tm1, __shfl_xor_sync(0xffffffffu, tm1, 1));
        tm1 = fmaxf(tm1, __shfl_xor_sync(0xffffffffu, tm1, 2));

        const float mn0 = fmaxf(m0r, tm0);
        const float mn1 = fmaxf(m1r, tm1);
        const float al0 = ex2(m0r - mn0);
        const float al1 = ex2(m1r - mn1);
        m0r = mn0; m1r = mn1;

        float sum0 = 0.0f, sum1 = 0.0f;
        uint32_t ph[8][2];
        #pragma unroll
        for (int nt = 0; nt < 8; nt++) {
            const float p0 = ex2(s[nt][0] - mn0);
            const float p1 = ex2(s[nt][1] - mn0);
            const float p2 = ex2(s[nt][2] - mn1);
            const float p3 = ex2(s[nt][3] - mn1);
            sum0 += p0 + p1;
            sum1 += p2 + p3;
            ph[nt][0] = pkh(p0, p1);
            ph[nt][1] = pkh(p2, p3);
        }
        sum0 += __shfl_xor_sync(0xffffffffu, sum0, 1);
        sum0 += __shfl_xor_sync(0xffffffffu, sum0, 2);
        sum1 += __shfl_xor_sync(0xffffffffu, sum1, 1);
        sum1 += __shfl_xor_sync(0xffffffffu, sum1, 2);
        l0r = l0r * al0 + sum0;
        l1r = l1r * al1 + sum1;

        #pragma unroll
        for (int nt = 0; nt < 8; nt++) {
            o[nt][0] *= al0; o[nt][1] *= al0;
            o[nt][2] *= al1; o[nt][3] *= al1;
        }

        // ---- O += P @ V (single product) ----
        #pragma unroll
        for (int j = 0; j < 4; j++) {
            uint32_t aPh[4] = { ph[2 * j][0], ph[2 * j][1],
                                ph[2 * j + 1][0], ph[2 * j + 1][1] };
            #pragma unroll
            for (int dp = 0; dp < 4; dp++) {
                uint32_t vh[4];
                const int cc = dp * 2 + (lane >> 4);
                const uint32_t voff = SWZ128((j * 16 + (lane & 15)) * 128 + cc * 16);
                ldsm_x4_t(vh, kv + AT_MAT + voff);
                mma_fp16(o[2 * dp + 0], aPh, vh[0], vh[1]);
                mma_fp16(o[2 * dp + 1], aPh, vh[2], vh[3]);
            }
        }
    }

    // ---- Normalize + write fp16 hi/lo to g_at [B,T,C] ----
    const float inv0 = 1.0f / l0r;
    const float inv1 = 1.0f / l1r;
    const int row0 = qt * 64 + w * 16 + (lane >> 2);
    #pragma unroll
    for (int nt = 0; nt < 8; nt++) {
        const int col = h * HDIM + nt * 8 + 2 * (lane & 3);
        const size_t o0 = ((size_t)b * TSEQ + row0) * CDIM + col;
        const size_t o1 = ((size_t)b * TSEQ + row0 + 8) * CDIM + col;
        const float v0 = o[nt][0] * inv0, v1 = o[nt][1] * inv0;
        const float v2 = o[nt][2] * inv1, v3 = o[nt][3] * inv1;
        const uint32_t h0 = pkh(v0, v1);
        const uint32_t h1 = pkh(v2, v3);
        *reinterpret_cast<uint32_t*>(&g_at_hi[o0]) = h0;
        *reinterpret_cast<uint32_t*>(&g_at_hi[o1]) = h1;
        *reinterpret_cast<uint32_t*>(&g_at_lo[o0]) =
            pkh(v0 - h_el0(h0), v1 - h_el1(h0));
        *reinterpret_cast<uint32_t*>(&g_at_lo[o1]) =
            pkh(v2 - h_el0(h1), v3 - h_el1(h1));
    }
}

// ---------------------------------------------------------------------------
// Launch
// ---------------------------------------------------------------------------
extern "C" void kernel_launch(void* const* d_in, const int* in_sizes, int n_in,
                              void* d_out, int out_size) {
    (void)in_sizes; (void)n_in; (void)out_size;
    const float* x      = (const float*)d_in[0];
    const float* w_qkv  = (const float*)d_in[1];
    const float* b_qkv  = (const float*)d_in[2];
    const float* w_proj = (const float*)d_in[3];
    const float* b_proj = (const float*)d_in[4];
    float* out = (float*)d_out;

    cudaFuncSetAttribute(mma_gemm<0>, cudaFuncAttributeMaxDynamicSharedMemorySize, GEMM_SMEM);
    cudaFuncSetAttribute(mma_gemm<1>, cudaFuncAttributeMaxDynamicSharedMemorySize, GEMM_SMEM);
    cudaFuncSetAttribute(attn_kernel, cudaFuncAttributeMaxDynamicSharedMemorySize, ATTN_SMEM);

    fp16 *x_hi, *x_lo, *wq, *wp, *at_hi, *at_lo;
    cudaGetSymbolAddress((void**)&x_hi,  g_x_hi);
    cudaGetSymbolAddress((void**)&x_lo,  g_x_lo);
    cudaGetSymbolAddress((void**)&wq,    g_wq);
    cudaGetSymbolAddress((void**)&wp,    g_wp);
    cudaGetSymbolAddress((void**)&at_hi, g_at_hi);
    cudaGetSymbolAddress((void**)&at_lo, g_at_lo);

    // Conversions
    split_kernel<<<4096, 256>>>(x, x_hi, x_lo, 4096 * 1024);
    transpose_h_kernel<<<dim3(96, 32), dim3(32, 8)>>>(w_qkv, wq, 1024, 3072);
    transpose_h_kernel<<<dim3(32, 32), dim3(32, 8)>>>(w_proj, wp, 1024, 1024);

    // QKV GEMM: M=4096, N=3072 -> grid (24, 32)
    mma_gemm<0><<<dim3(24, 32), 256, GEMM_SMEM>>>(x_hi, x_lo, wq, b_qkv, nullptr);

    // Attention: (32 q-tiles, 16 heads, 2 batch)
    attn_kernel<<<dim3(32, NHEAD, BATCH), 128, ATTN_SMEM>>>();

    // Projection: M=4096, N=1024 -> grid (8, 32)
    mma_gemm<1><<<dim3(8, 32), 256, GEMM_SMEM>>>(at_hi, at_lo, wp, b_proj, out);
}